// round 1
// baseline (speedup 1.0000x reference)
#include <cuda_runtime.h>
#include <cuda_bf16.h>
#include <math.h>

// Problem constants
#define BATCH 2
#define SEQ   2048
#define EMB   1024
#define NHEAD 16
#define HDIM  64
#define STRIDE_BLK 128
#define CKEEP 8

// Scratch (device globals; no runtime allocation allowed)
__device__ float g_qkv[(size_t)BATCH * SEQ * 3 * EMB];   // [B,S,3E]  ~50 MB
__device__ float g_att[(size_t)BATCH * SEQ * EMB];       // [B,S,E]   ~16 MB

// ---------------------------------------------------------------------------
// Tiled SGEMM with bias: C[M,N] = A[M,K] @ B[K,N] + bias[N]
// BM=128, BN=128, BK=8, 256 threads, 8x8 per-thread microtile.
// Requires M%128==0, N%128==0, K%8==0 (true for all shapes here).
// ---------------------------------------------------------------------------
#define BM 128
#define BN 128
#define BK 8
#define TM 8
#define TN 8

__global__ __launch_bounds__(256) void sgemm_bias(
    const float* __restrict__ A, const float* __restrict__ B,
    const float* __restrict__ bias, float* __restrict__ C,
    int M, int N, int K)
{
    __shared__ float As[BK][BM];
    __shared__ float Bs[BK][BN];

    const int tid  = threadIdx.x;
    const int brow = blockIdx.y;   // M tile index
    const int bcol = blockIdx.x;   // N tile index

    const int tcol = tid % (BN / TN);  // 0..15
    const int trow = tid / (BN / TN);  // 0..15

    // A tile load mapping: 128 rows x 8 cols = 256 float4 (one per thread)
    const int aRow = tid >> 1;          // 0..127
    const int aCol = (tid & 1) << 2;    // 0 or 4
    // B tile load mapping: 8 rows x 128 cols = 256 float4
    const int bRow = tid >> 5;          // 0..7
    const int bCol = (tid & 31) << 2;   // 0..124

    const float* Ablk = A + (size_t)brow * BM * K;
    const float* Bblk = B + (size_t)bcol * BN;

    float acc[TM][TN] = {};
    float regM[TM], regN[TN];

    for (int k0 = 0; k0 < K; k0 += BK) {
        float4 a4 = *reinterpret_cast<const float4*>(Ablk + (size_t)aRow * K + k0 + aCol);
        As[aCol + 0][aRow] = a4.x;
        As[aCol + 1][aRow] = a4.y;
        As[aCol + 2][aRow] = a4.z;
        As[aCol + 3][aRow] = a4.w;
        *reinterpret_cast<float4*>(&Bs[bRow][bCol]) =
            *reinterpret_cast<const float4*>(Bblk + (size_t)(k0 + bRow) * N + bCol);
        __syncthreads();

        #pragma unroll
        for (int k = 0; k < BK; k++) {
            #pragma unroll
            for (int i = 0; i < TM; i++) regM[i] = As[k][trow * TM + i];
            #pragma unroll
            for (int j = 0; j < TN; j++) regN[j] = Bs[k][tcol * TN + j];
            #pragma unroll
            for (int i = 0; i < TM; i++)
                #pragma unroll
                for (int j = 0; j < TN; j++)
                    acc[i][j] += regM[i] * regN[j];
        }
        __syncthreads();
    }

    const int cN = bcol * BN + tcol * TN;
    #pragma unroll
    for (int i = 0; i < TM; i++) {
        const int row = brow * BM + trow * TM + i;
        float* Crow = C + (size_t)row * N + cN;
        #pragma unroll
        for (int j = 0; j < TN; j++)
            Crow[j] = acc[i][j] + bias[cN + j];
    }
}

// ---------------------------------------------------------------------------
// Sparse-causal attention, exploiting the closed-form mask structure.
// For query q: allowed keys = {blk*128 + 120..127 : blk < q/128}  (strided)
//                          ∪ {q/128*128 .. q}                     (local causal)
// One block per (b,h,q); 128 threads. Max key count = 128 + 8*15 = 248.
// ---------------------------------------------------------------------------
__global__ __launch_bounds__(128) void sparse_attn(
    const float* __restrict__ qkv, float* __restrict__ out)
{
    const int q   = blockIdx.x;
    const int h   = blockIdx.y;
    const int b   = blockIdx.z;
    const int tid = threadIdx.x;
    const float scale = 0.125f;  // 1/sqrt(64)

    __shared__ float qv[HDIM];
    __shared__ float sc[256];
    __shared__ float red[128];

    const float* qrow = qkv + ((size_t)(b * SEQ + q)) * (3 * EMB) + h * HDIM;
    if (tid < HDIM) qv[tid] = qrow[tid];
    __syncthreads();

    const int nb   = q >> 7;           // number of earlier stride blocks
    const int nstr = nb * CKEEP;       // strided key count
    const int cnt  = nstr + (q & 127) + 1;

    const float* Kbase = qkv + (size_t)b * SEQ * (3 * EMB) + EMB + h * HDIM;
    const float* Vbase = qkv + (size_t)b * SEQ * (3 * EMB) + 2 * EMB + h * HDIM;

    // --- scores ---
    float lmax = -INFINITY;
    for (int j = tid; j < cnt; j += 128) {
        const int key = (j < nstr) ? ((j >> 3) << 7) + (STRIDE_BLK - CKEEP) + (j & 7)
                                   : (nb << 7) + (j - nstr);
        const float* kr = Kbase + (size_t)key * (3 * EMB);
        float dot = 0.f;
        #pragma unroll
        for (int d = 0; d < HDIM; d++) dot += qv[d] * kr[d];
        dot *= scale;
        sc[j] = dot;
        lmax = fmaxf(lmax, dot);
    }
    red[tid] = lmax;
    __syncthreads();
    #pragma unroll
    for (int s = 64; s > 0; s >>= 1) {
        if (tid < s) red[tid] = fmaxf(red[tid], red[tid + s]);
        __syncthreads();
    }
    const float mx = red[0];
    __syncthreads();

    // --- exp + sum ---
    float lsum = 0.f;
    for (int j = tid; j < cnt; j += 128) {
        const float e = __expf(sc[j] - mx);
        sc[j] = e;
        lsum += e;
    }
    red[tid] = lsum;
    __syncthreads();
    #pragma unroll
    for (int s = 64; s > 0; s >>= 1) {
        if (tid < s) red[tid] += red[tid + s];
        __syncthreads();
    }
    const float inv = 1.0f / red[0];
    __syncthreads();

    // --- weighted V accumulation: thread (half, d) ---
    const int d    = tid & 63;
    const int half = tid >> 6;
    float acc = 0.f;
    for (int j = half; j < cnt; j += 2) {
        const int key = (j < nstr) ? ((j >> 3) << 7) + (STRIDE_BLK - CKEEP) + (j & 7)
                                   : (nb << 7) + (j - nstr);
        acc += sc[j] * Vbase[(size_t)key * (3 * EMB) + d];
    }
    red[tid] = acc;
    __syncthreads();
    if (tid < 64) {
        out[((size_t)(b * SEQ + q)) * EMB + h * HDIM + d] =
            (red[tid] + red[tid + 64]) * inv;
    }
}

// ---------------------------------------------------------------------------
extern "C" void kernel_launch(void* const* d_in, const int* in_sizes, int n_in,
                              void* d_out, int out_size) {
    const float* hs     = (const float*)d_in[0];  // [B,S,E]
    const float* W_attn = (const float*)d_in[1];  // [E,3E]
    const float* b_attn = (const float*)d_in[2];  // [3E]
    const float* W_proj = (const float*)d_in[3];  // [E,E]
    const float* b_proj = (const float*)d_in[4];  // [E]
    float* out = (float*)d_out;                   // [B,S,E]

    float *qkv, *att;
    cudaGetSymbolAddress((void**)&qkv, g_qkv);
    cudaGetSymbolAddress((void**)&att, g_att);

    const int M = BATCH * SEQ;  // 4096

    // 1) QKV projection: [4096,1024] @ [1024,3072] + bias
    {
        dim3 grid((3 * EMB) / BN, M / BM);
        sgemm_bias<<<grid, 256>>>(hs, W_attn, b_attn, qkv, M, 3 * EMB, EMB);
    }
    // 2) Sparse attention -> merged heads [B,S,E]
    {
        dim3 grid(SEQ, NHEAD, BATCH);
        sparse_attn<<<grid, 128>>>(qkv, att);
    }
    // 3) Output projection: [4096,1024] @ [1024,1024] + bias
    {
        dim3 grid(EMB / BN, M / BM);
        sgemm_bias<<<grid, 256>>>(att, W_proj, b_proj, out, M, EMB, EMB);
    }
}

// round 2
// speedup vs baseline: 2.7985x; 2.7985x over previous
#include <cuda_runtime.h>
#include <cuda_bf16.h>
#include <math.h>

// Problem constants
#define BATCH 2
#define SEQ   2048
#define EMB   1024
#define NHEAD 16
#define HDIM  64
#define STRIDE_BLK 128
#define CKEEP 8

// Scratch (device globals; no runtime allocation allowed)
__device__ float g_qkv[(size_t)BATCH * SEQ * 3 * EMB];   // [B,S,3E]  ~50 MB
__device__ float g_att[(size_t)BATCH * SEQ * EMB];       // [B,S,E]   ~16 MB

// ---------------------------------------------------------------------------
// Tiled SGEMM with bias: C[M,N] = A[M,K] @ B[K,N] + bias[N]
// ---------------------------------------------------------------------------
#define BM 128
#define BN 128
#define BK 8
#define TM 8
#define TN 8

__global__ __launch_bounds__(256) void sgemm_bias(
    const float* __restrict__ A, const float* __restrict__ B,
    const float* __restrict__ bias, float* __restrict__ C,
    int M, int N, int K)
{
    __shared__ float As[BK][BM];
    __shared__ float Bs[BK][BN];

    const int tid  = threadIdx.x;
    const int brow = blockIdx.y;
    const int bcol = blockIdx.x;

    const int tcol = tid % (BN / TN);
    const int trow = tid / (BN / TN);

    const int aRow = tid >> 1;
    const int aCol = (tid & 1) << 2;
    const int bRow = tid >> 5;
    const int bCol = (tid & 31) << 2;

    const float* Ablk = A + (size_t)brow * BM * K;
    const float* Bblk = B + (size_t)bcol * BN;

    float acc[TM][TN] = {};
    float regM[TM], regN[TN];

    for (int k0 = 0; k0 < K; k0 += BK) {
        float4 a4 = *reinterpret_cast<const float4*>(Ablk + (size_t)aRow * K + k0 + aCol);
        As[aCol + 0][aRow] = a4.x;
        As[aCol + 1][aRow] = a4.y;
        As[aCol + 2][aRow] = a4.z;
        As[aCol + 3][aRow] = a4.w;
        *reinterpret_cast<float4*>(&Bs[bRow][bCol]) =
            *reinterpret_cast<const float4*>(Bblk + (size_t)(k0 + bRow) * N + bCol);
        __syncthreads();

        #pragma unroll
        for (int k = 0; k < BK; k++) {
            #pragma unroll
            for (int i = 0; i < TM; i++) regM[i] = As[k][trow * TM + i];
            #pragma unroll
            for (int j = 0; j < TN; j++) regN[j] = Bs[k][tcol * TN + j];
            #pragma unroll
            for (int i = 0; i < TM; i++)
                #pragma unroll
                for (int j = 0; j < TN; j++)
                    acc[i][j] += regM[i] * regN[j];
        }
        __syncthreads();
    }

    const int cN = bcol * BN + tcol * TN;
    #pragma unroll
    for (int i = 0; i < TM; i++) {
        const int row = brow * BM + trow * TM + i;
        float* Crow = C + (size_t)row * N + cN;
        #pragma unroll
        for (int j = 0; j < TN; j++)
            Crow[j] = acc[i][j] + bias[cN + j];
    }
}

// ---------------------------------------------------------------------------
// Tiled sparse-causal attention.
// One CTA per (b, h, 64-query half of a 128-stride block). All queries in a
// stride block share the same key set:
//   strided keys: {blk*128+120..127 : blk < qb}   (nstr = 8*qb keys)
//   local keys:   {qb*128 .. qb*128+127}          (causal-limited per row)
// Key j (0..cnt-1), cnt = nstr+128. Validity: col <= nstr + (q mod 128).
// 256 threads. Q/K staged transposed in smem; full 64x256 score matrix in
// smem; masked softmax; P@V with 4x4 microtile.
// ---------------------------------------------------------------------------
#define QS_SZ   (64 * 64)       // Qs[d][r]
#define KS_SZ   (64 * 256)      // Ks[d][j]
#define VS_STR  68
#define VS_SZ   (256 * VS_STR)  // Vs[j][d] padded
#define SS_STR  260
#define SS_SZ   (64 * SS_STR)   // Ss[r][j] padded
#define ATTN_SMEM_FLOATS (QS_SZ + KS_SZ + VS_SZ + SS_SZ + 64)
#define ATTN_SMEM_BYTES  (ATTN_SMEM_FLOATS * 4)

__global__ __launch_bounds__(256, 1) void sparse_attn_tiled(
    const float* __restrict__ qkv, float* __restrict__ out)
{
    const int bq  = blockIdx.x;        // 0..31 : qb*2 + hb
    const int h   = blockIdx.y;
    const int b   = blockIdx.z;
    const int qb  = bq >> 1;
    const int hb  = bq & 1;
    const int tid = threadIdx.x;

    const int nstr = qb * CKEEP;       // strided key count
    const int cnt  = nstr + 128;       // total keys for this stride block

    extern __shared__ float sm[];
    float* Qs   = sm;                  // [64][64]   (d-major)
    float* Ks   = Qs + QS_SZ;          // [64][256]  (d-major)
    float* Vs   = Ks + KS_SZ;          // [256][68]  (key-major)
    float* Ss   = Vs + VS_SZ;          // [64][260]
    float* Linv = Ss + SS_SZ;          // [64]

    const size_t base = (size_t)b * SEQ * (3 * EMB);
    const int q0 = qb * 128 + hb * 64;

    // --- stage Q transposed: Qs[d][r] ---
    {
        const int r  = tid >> 2;             // 0..63
        const int d0 = (tid & 3) * 16;       // 0,16,32,48
        const float* src = qkv + base + (size_t)(q0 + r) * (3 * EMB) + h * HDIM + d0;
        #pragma unroll
        for (int i = 0; i < 4; i++) {
            float4 a = *reinterpret_cast<const float4*>(src + i * 4);
            const int d = d0 + i * 4;
            Qs[(d + 0) * 64 + r] = a.x;
            Qs[(d + 1) * 64 + r] = a.y;
            Qs[(d + 2) * 64 + r] = a.z;
            Qs[(d + 3) * 64 + r] = a.w;
        }
    }

    // --- stage K (transposed) and V (row-major): thread j = key index ---
    {
        const int j = tid;
        if (j < cnt) {
            const int key = (j < nstr)
                ? ((j >> 3) << 7) + (STRIDE_BLK - CKEEP) + (j & 7)
                : (qb << 7) + (j - nstr);
            const float* ksrc = qkv + base + (size_t)key * (3 * EMB) + EMB + h * HDIM;
            const float* vsrc = qkv + base + (size_t)key * (3 * EMB) + 2 * EMB + h * HDIM;
            #pragma unroll
            for (int i = 0; i < 16; i++) {
                float4 a = *reinterpret_cast<const float4*>(ksrc + i * 4);
                Ks[(i * 4 + 0) * 256 + j] = a.x;
                Ks[(i * 4 + 1) * 256 + j] = a.y;
                Ks[(i * 4 + 2) * 256 + j] = a.z;
                Ks[(i * 4 + 3) * 256 + j] = a.w;
                float4 v = *reinterpret_cast<const float4*>(vsrc + i * 4);
                *reinterpret_cast<float4*>(Vs + j * VS_STR + i * 4) = v;
            }
        }
    }
    __syncthreads();

    // --- scores: S[64][256] = Q @ K^T, 8x8 microtile, thread grid 8x32 ---
    {
        const int trow = tid >> 5;   // 0..7  -> rows trow*8..+7
        const int tcol = tid & 31;   // 0..31 -> cols tcol*8..+7
        float acc[8][8] = {};
        float rm[8], rn[8];
        #pragma unroll 4
        for (int k = 0; k < HDIM; k++) {
            *reinterpret_cast<float4*>(rm)     = *reinterpret_cast<const float4*>(Qs + k * 64 + trow * 8);
            *reinterpret_cast<float4*>(rm + 4) = *reinterpret_cast<const float4*>(Qs + k * 64 + trow * 8 + 4);
            *reinterpret_cast<float4*>(rn)     = *reinterpret_cast<const float4*>(Ks + k * 256 + tcol * 8);
            *reinterpret_cast<float4*>(rn + 4) = *reinterpret_cast<const float4*>(Ks + k * 256 + tcol * 8 + 4);
            #pragma unroll
            for (int i = 0; i < 8; i++)
                #pragma unroll
                for (int j = 0; j < 8; j++)
                    acc[i][j] += rm[i] * rn[j];
        }
        // masked write: valid <=> col <= nstr + (q mod 128)
        #pragma unroll
        for (int i = 0; i < 8; i++) {
            const int r   = trow * 8 + i;
            const int lim = nstr + hb * 64 + r;
            float* srow = Ss + r * SS_STR + tcol * 8;
            #pragma unroll
            for (int j = 0; j < 8; j++) {
                const int c = tcol * 8 + j;
                srow[j] = (c <= lim) ? acc[i][j] * 0.125f : -1e30f;
            }
        }
    }
    __syncthreads();

    // --- softmax per row: 4 threads/row, stride-4 scan, shfl combine ---
    {
        const int row = tid >> 2;
        const int sub = tid & 3;
        float* srow = Ss + row * SS_STR;
        float m = -1e30f;
        for (int c = sub; c < cnt; c += 4) m = fmaxf(m, srow[c]);
        m = fmaxf(m, __shfl_xor_sync(0xffffffffu, m, 1));
        m = fmaxf(m, __shfl_xor_sync(0xffffffffu, m, 2));
        float s = 0.f;
        for (int c = sub; c < cnt; c += 4) {
            const float e = __expf(srow[c] - m);
            srow[c] = e;
            s += e;
        }
        s += __shfl_xor_sync(0xffffffffu, s, 1);
        s += __shfl_xor_sync(0xffffffffu, s, 2);
        if (sub == 0) Linv[row] = 1.0f / s;
    }
    __syncthreads();

    // --- O[64][64] = P @ V, 4x4 microtile, thread grid 16x16 ---
    {
        const int rg = tid >> 4;    // 0..15 -> rows rg*4..+3
        const int cg = tid & 15;    // 0..15 -> cols cg*4..+3
        float acc[4][4] = {};
        #pragma unroll 2
        for (int kk = 0; kk < cnt; kk++) {
            const float4 v = *reinterpret_cast<const float4*>(Vs + kk * VS_STR + cg * 4);
            #pragma unroll
            for (int i = 0; i < 4; i++) {
                const float p = Ss[(rg * 4 + i) * SS_STR + kk];
                acc[i][0] += p * v.x;
                acc[i][1] += p * v.y;
                acc[i][2] += p * v.z;
                acc[i][3] += p * v.w;
            }
        }
        #pragma unroll
        for (int i = 0; i < 4; i++) {
            const int r = rg * 4 + i;
            const float inv = Linv[r];
            float4 o;
            o.x = acc[i][0] * inv;
            o.y = acc[i][1] * inv;
            o.z = acc[i][2] * inv;
            o.w = acc[i][3] * inv;
            *reinterpret_cast<float4*>(
                out + (size_t)(b * SEQ + q0 + r) * EMB + h * HDIM + cg * 4) = o;
        }
    }
}

// ---------------------------------------------------------------------------
extern "C" void kernel_launch(void* const* d_in, const int* in_sizes, int n_in,
                              void* d_out, int out_size) {
    const float* hs     = (const float*)d_in[0];  // [B,S,E]
    const float* W_attn = (const float*)d_in[1];  // [E,3E]
    const float* b_attn = (const float*)d_in[2];  // [3E]
    const float* W_proj = (const float*)d_in[3];  // [E,E]
    const float* b_proj = (const float*)d_in[4];  // [E]
    float* out = (float*)d_out;                   // [B,S,E]

    float *qkv, *att;
    cudaGetSymbolAddress((void**)&qkv, g_qkv);
    cudaGetSymbolAddress((void**)&att, g_att);

    static bool attr_set = false;
    if (!attr_set) {
        cudaFuncSetAttribute(sparse_attn_tiled,
                             cudaFuncAttributeMaxDynamicSharedMemorySize,
                             ATTN_SMEM_BYTES);
        attr_set = true;
    }

    const int M = BATCH * SEQ;  // 4096

    // 1) QKV projection: [4096,1024] @ [1024,3072] + bias
    {
        dim3 grid((3 * EMB) / BN, M / BM);
        sgemm_bias<<<grid, 256>>>(hs, W_attn, b_attn, qkv, M, 3 * EMB, EMB);
    }
    // 2) Sparse attention -> merged heads [B,S,E]
    {
        dim3 grid(32, NHEAD, BATCH);
        sparse_attn_tiled<<<grid, 256, ATTN_SMEM_BYTES>>>(qkv, att);
    }
    // 3) Output projection: [4096,1024] @ [1024,1024] + bias
    {
        dim3 grid(EMB / BN, M / BM);
        sgemm_bias<<<grid, 256>>>(att, W_proj, b_proj, out, M, EMB, EMB);
    }
}

// round 3
// speedup vs baseline: 2.9467x; 1.0530x over previous
#include <cuda_runtime.h>
#include <cuda_bf16.h>
#include <math.h>

// Problem constants
#define BATCH 2
#define SEQ   2048
#define EMB   1024
#define NHEAD 16
#define HDIM  64
#define STRIDE_BLK 128
#define CKEEP 8

// Scratch (device globals; no runtime allocation allowed)
__device__ float g_qkv[(size_t)BATCH * SEQ * 3 * EMB];   // [B,S,3E]  ~50 MB
__device__ float g_att[(size_t)BATCH * SEQ * EMB];       // [B,S,E]   ~16 MB

// ---------------------------------------------------------------------------
// Packed f32x2 helpers (sm_103a): FFMA2 is only reachable via PTX.
// ---------------------------------------------------------------------------
__device__ __forceinline__ unsigned long long pack2(float x, float y) {
    unsigned long long d;
    asm("mov.b64 %0, {%1, %2};" : "=l"(d) : "f"(x), "f"(y));
    return d;
}
__device__ __forceinline__ void unpack2(unsigned long long v, float& lo, float& hi) {
    asm("mov.b64 {%0, %1}, %2;" : "=f"(lo), "=f"(hi) : "l"(v));
}
__device__ __forceinline__ unsigned long long ffma2(
    unsigned long long a, unsigned long long b, unsigned long long c) {
    unsigned long long d;
    asm("fma.rn.f32x2 %0, %1, %2, %3;" : "=l"(d) : "l"(a), "l"(b), "l"(c));
    return d;
}

// ---------------------------------------------------------------------------
// Tiled SGEMM with bias, FFMA2 inner product, double-buffered smem.
// C[M,N] = A[M,K] @ B[K,N] + bias[N].  BM=BN=128, BK=8, 256 thr, 8x8 microtile.
// ---------------------------------------------------------------------------
#define BM 128
#define BN 128
#define BK 8
#define TM 8
#define TN 8

__global__ __launch_bounds__(256) void sgemm_bias(
    const float* __restrict__ A, const float* __restrict__ B,
    const float* __restrict__ bias, float* __restrict__ C,
    int M, int N, int K)
{
    __shared__ float As[2][BK][BM];
    __shared__ float Bs[2][BK][BN];

    const int tid  = threadIdx.x;
    const int brow = blockIdx.y;
    const int bcol = blockIdx.x;

    const int tcol = tid % (BN / TN);   // 0..15
    const int trow = tid / (BN / TN);   // 0..15

    const int aRow = tid >> 1;          // 0..127
    const int aCol = (tid & 1) << 2;    // 0 or 4
    const int bRow = tid >> 5;          // 0..7
    const int bCol = (tid & 31) << 2;   // 0..124

    const float* Ablk = A + (size_t)brow * BM * K;
    const float* Bblk = B + (size_t)bcol * BN;

    // acc2[i][j] holds C rows trow*8+i, cols {tcol*8+2j, +2j+1}
    unsigned long long acc2[TM][TN / 2] = {};

    // --- stage tile 0 ---
    {
        float4 a4 = *reinterpret_cast<const float4*>(Ablk + (size_t)aRow * K + aCol);
        As[0][aCol + 0][aRow] = a4.x;
        As[0][aCol + 1][aRow] = a4.y;
        As[0][aCol + 2][aRow] = a4.z;
        As[0][aCol + 3][aRow] = a4.w;
        *reinterpret_cast<float4*>(&Bs[0][bRow][bCol]) =
            *reinterpret_cast<const float4*>(Bblk + (size_t)bRow * N + bCol);
    }
    __syncthreads();

    int buf = 0;
    for (int k0 = 0; k0 < K; k0 += BK) {
        // prefetch next tile into registers
        float4 a_pref, b_pref;
        const bool more = (k0 + BK) < K;
        if (more) {
            a_pref = *reinterpret_cast<const float4*>(Ablk + (size_t)aRow * K + k0 + BK + aCol);
            b_pref = *reinterpret_cast<const float4*>(Bblk + (size_t)(k0 + BK + bRow) * N + bCol);
        }

        #pragma unroll
        for (int k = 0; k < BK; k++) {
            float4 m0 = *reinterpret_cast<const float4*>(&As[buf][k][trow * TM]);
            float4 m1 = *reinterpret_cast<const float4*>(&As[buf][k][trow * TM + 4]);
            float4 n0 = *reinterpret_cast<const float4*>(&Bs[buf][k][tcol * TN]);
            float4 n1 = *reinterpret_cast<const float4*>(&Bs[buf][k][tcol * TN + 4]);
            unsigned long long rn2[4];
            rn2[0] = pack2(n0.x, n0.y);
            rn2[1] = pack2(n0.z, n0.w);
            rn2[2] = pack2(n1.x, n1.y);
            rn2[3] = pack2(n1.z, n1.w);
            float rm[TM] = {m0.x, m0.y, m0.z, m0.w, m1.x, m1.y, m1.z, m1.w};
            #pragma unroll
            for (int i = 0; i < TM; i++) {
                const unsigned long long rm2 = pack2(rm[i], rm[i]);
                #pragma unroll
                for (int j = 0; j < TN / 2; j++)
                    acc2[i][j] = ffma2(rm2, rn2[j], acc2[i][j]);
            }
        }

        if (more) {
            const int nb = buf ^ 1;
            As[nb][aCol + 0][aRow] = a_pref.x;
            As[nb][aCol + 1][aRow] = a_pref.y;
            As[nb][aCol + 2][aRow] = a_pref.z;
            As[nb][aCol + 3][aRow] = a_pref.w;
            *reinterpret_cast<float4*>(&Bs[nb][bRow][bCol]) = b_pref;
            __syncthreads();
        }
        buf ^= 1;
    }

    const int cN = bcol * BN + tcol * TN;
    float4 bi0 = *reinterpret_cast<const float4*>(bias + cN);
    float4 bi1 = *reinterpret_cast<const float4*>(bias + cN + 4);
    const float bb[TN] = {bi0.x, bi0.y, bi0.z, bi0.w, bi1.x, bi1.y, bi1.z, bi1.w};

    #pragma unroll
    for (int i = 0; i < TM; i++) {
        const int row = brow * BM + trow * TM + i;
        float o[TN];
        #pragma unroll
        for (int j = 0; j < TN / 2; j++)
            unpack2(acc2[i][j], o[2 * j], o[2 * j + 1]);
        float4 r0, r1;
        r0.x = o[0] + bb[0]; r0.y = o[1] + bb[1]; r0.z = o[2] + bb[2]; r0.w = o[3] + bb[3];
        r1.x = o[4] + bb[4]; r1.y = o[5] + bb[5]; r1.z = o[6] + bb[6]; r1.w = o[7] + bb[7];
        float* Crow = C + (size_t)row * N + cN;
        *reinterpret_cast<float4*>(Crow)     = r0;
        *reinterpret_cast<float4*>(Crow + 4) = r1;
    }
}

// ---------------------------------------------------------------------------
// Tiled sparse-causal attention (unchanged from R2 — ~150us, not the bottleneck)
// ---------------------------------------------------------------------------
#define QS_SZ   (64 * 64)
#define KS_SZ   (64 * 256)
#define VS_STR  68
#define VS_SZ   (256 * VS_STR)
#define SS_STR  260
#define SS_SZ   (64 * SS_STR)
#define ATTN_SMEM_FLOATS (QS_SZ + KS_SZ + VS_SZ + SS_SZ + 64)
#define ATTN_SMEM_BYTES  (ATTN_SMEM_FLOATS * 4)

__global__ __launch_bounds__(256, 1) void sparse_attn_tiled(
    const float* __restrict__ qkv, float* __restrict__ out)
{
    const int bq  = blockIdx.x;
    const int h   = blockIdx.y;
    const int b   = blockIdx.z;
    const int qb  = bq >> 1;
    const int hb  = bq & 1;
    const int tid = threadIdx.x;

    const int nstr = qb * CKEEP;
    const int cnt  = nstr + 128;

    extern __shared__ float sm[];
    float* Qs   = sm;
    float* Ks   = Qs + QS_SZ;
    float* Vs   = Ks + KS_SZ;
    float* Ss   = Vs + VS_SZ;
    float* Linv = Ss + SS_SZ;

    const size_t base = (size_t)b * SEQ * (3 * EMB);
    const int q0 = qb * 128 + hb * 64;

    {
        const int r  = tid >> 2;
        const int d0 = (tid & 3) * 16;
        const float* src = qkv + base + (size_t)(q0 + r) * (3 * EMB) + h * HDIM + d0;
        #pragma unroll
        for (int i = 0; i < 4; i++) {
            float4 a = *reinterpret_cast<const float4*>(src + i * 4);
            const int d = d0 + i * 4;
            Qs[(d + 0) * 64 + r] = a.x;
            Qs[(d + 1) * 64 + r] = a.y;
            Qs[(d + 2) * 64 + r] = a.z;
            Qs[(d + 3) * 64 + r] = a.w;
        }
    }

    {
        const int j = tid;
        if (j < cnt) {
            const int key = (j < nstr)
                ? ((j >> 3) << 7) + (STRIDE_BLK - CKEEP) + (j & 7)
                : (qb << 7) + (j - nstr);
            const float* ksrc = qkv + base + (size_t)key * (3 * EMB) + EMB + h * HDIM;
            const float* vsrc = qkv + base + (size_t)key * (3 * EMB) + 2 * EMB + h * HDIM;
            #pragma unroll
            for (int i = 0; i < 16; i++) {
                float4 a = *reinterpret_cast<const float4*>(ksrc + i * 4);
                Ks[(i * 4 + 0) * 256 + j] = a.x;
                Ks[(i * 4 + 1) * 256 + j] = a.y;
                Ks[(i * 4 + 2) * 256 + j] = a.z;
                Ks[(i * 4 + 3) * 256 + j] = a.w;
                float4 v = *reinterpret_cast<const float4*>(vsrc + i * 4);
                *reinterpret_cast<float4*>(Vs + j * VS_STR + i * 4) = v;
            }
        }
    }
    __syncthreads();

    {
        const int trow = tid >> 5;
        const int tcol = tid & 31;
        float acc[8][8] = {};
        float rm[8], rn[8];
        #pragma unroll 4
        for (int k = 0; k < HDIM; k++) {
            *reinterpret_cast<float4*>(rm)     = *reinterpret_cast<const float4*>(Qs + k * 64 + trow * 8);
            *reinterpret_cast<float4*>(rm + 4) = *reinterpret_cast<const float4*>(Qs + k * 64 + trow * 8 + 4);
            *reinterpret_cast<float4*>(rn)     = *reinterpret_cast<const float4*>(Ks + k * 256 + tcol * 8);
            *reinterpret_cast<float4*>(rn + 4) = *reinterpret_cast<const float4*>(Ks + k * 256 + tcol * 8 + 4);
            #pragma unroll
            for (int i = 0; i < 8; i++)
                #pragma unroll
                for (int j = 0; j < 8; j++)
                    acc[i][j] += rm[i] * rn[j];
        }
        #pragma unroll
        for (int i = 0; i < 8; i++) {
            const int r   = trow * 8 + i;
            const int lim = nstr + hb * 64 + r;
            float* srow = Ss + r * SS_STR + tcol * 8;
            #pragma unroll
            for (int j = 0; j < 8; j++) {
                const int c = tcol * 8 + j;
                srow[j] = (c <= lim) ? acc[i][j] * 0.125f : -1e30f;
            }
        }
    }
    __syncthreads();

    {
        const int row = tid >> 2;
        const int sub = tid & 3;
        float* srow = Ss + row * SS_STR;
        float m = -1e30f;
        for (int c = sub; c < cnt; c += 4) m = fmaxf(m, srow[c]);
        m = fmaxf(m, __shfl_xor_sync(0xffffffffu, m, 1));
        m = fmaxf(m, __shfl_xor_sync(0xffffffffu, m, 2));
        float s = 0.f;
        for (int c = sub; c < cnt; c += 4) {
            const float e = __expf(srow[c] - m);
            srow[c] = e;
            s += e;
        }
        s += __shfl_xor_sync(0xffffffffu, s, 1);
        s += __shfl_xor_sync(0xffffffffu, s, 2);
        if (sub == 0) Linv[row] = 1.0f / s;
    }
    __syncthreads();

    {
        const int rg = tid >> 4;
        const int cg = tid & 15;
        float acc[4][4] = {};
        #pragma unroll 2
        for (int kk = 0; kk < cnt; kk++) {
            const float4 v = *reinterpret_cast<const float4*>(Vs + kk * VS_STR + cg * 4);
            #pragma unroll
            for (int i = 0; i < 4; i++) {
                const float p = Ss[(rg * 4 + i) * SS_STR + kk];
                acc[i][0] += p * v.x;
                acc[i][1] += p * v.y;
                acc[i][2] += p * v.z;
                acc[i][3] += p * v.w;
            }
        }
        #pragma unroll
        for (int i = 0; i < 4; i++) {
            const int r = rg * 4 + i;
            const float inv = Linv[r];
            float4 o;
            o.x = acc[i][0] * inv;
            o.y = acc[i][1] * inv;
            o.z = acc[i][2] * inv;
            o.w = acc[i][3] * inv;
            *reinterpret_cast<float4*>(
                out + (size_t)(b * SEQ + q0 + r) * EMB + h * HDIM + cg * 4) = o;
        }
    }
}

// ---------------------------------------------------------------------------
extern "C" void kernel_launch(void* const* d_in, const int* in_sizes, int n_in,
                              void* d_out, int out_size) {
    const float* hs     = (const float*)d_in[0];
    const float* W_attn = (const float*)d_in[1];
    const float* b_attn = (const float*)d_in[2];
    const float* W_proj = (const float*)d_in[3];
    const float* b_proj = (const float*)d_in[4];
    float* out = (float*)d_out;

    float *qkv, *att;
    cudaGetSymbolAddress((void**)&qkv, g_qkv);
    cudaGetSymbolAddress((void**)&att, g_att);

    static bool attr_set = false;
    if (!attr_set) {
        cudaFuncSetAttribute(sparse_attn_tiled,
                             cudaFuncAttributeMaxDynamicSharedMemorySize,
                             ATTN_SMEM_BYTES);
        attr_set = true;
    }

    const int M = BATCH * SEQ;  // 4096

    // 1) QKV projection: [4096,1024] @ [1024,3072] + bias
    {
        dim3 grid((3 * EMB) / BN, M / BM);
        sgemm_bias<<<grid, 256>>>(hs, W_attn, b_attn, qkv, M, 3 * EMB, EMB);
    }
    // 2) Sparse attention -> merged heads [B,S,E]
    {
        dim3 grid(32, NHEAD, BATCH);
        sparse_attn_tiled<<<grid, 256, ATTN_SMEM_BYTES>>>(qkv, att);
    }
    // 3) Output projection: [4096,1024] @ [1024,1024] + bias
    {
        dim3 grid(EMB / BN, M / BM);
        sgemm_bias<<<grid, 256>>>(att, W_proj, b_proj, out, M, EMB, EMB);
    }
}

// round 4
// speedup vs baseline: 6.0087x; 2.0392x over previous
#include <cuda_runtime.h>
#include <cuda_bf16.h>
#include <math.h>
#include <stdint.h>

// Problem constants
#define BATCH 2
#define SEQ   2048
#define EMB   1024
#define NHEAD 16
#define HDIM  64
#define STRIDE_BLK 128
#define CKEEP 8

// Scratch (device globals; no runtime allocation allowed)
__device__ float g_qkv[(size_t)BATCH * SEQ * 3 * EMB];         // [B,S,3E]
__device__ float g_att[(size_t)BATCH * SEQ * EMB];             // [B,S,E]
__device__ __nv_bfloat16 g_AH[(size_t)4096 * 1024];            // A hi (hs or att)
__device__ __nv_bfloat16 g_AL[(size_t)4096 * 1024];            // A lo
__device__ __nv_bfloat16 g_WH[(size_t)3072 * 1024];            // W^T hi [N][K]
__device__ __nv_bfloat16 g_WL[(size_t)3072 * 1024];            // W^T lo

// ---------------------------------------------------------------------------
// fp32 -> (bf16 hi, bf16 lo) split, elementwise (A matrices, row-major [M][K])
// ---------------------------------------------------------------------------
__global__ __launch_bounds__(256) void conv_split(
    const float* __restrict__ X, __nv_bfloat16* __restrict__ Hi,
    __nv_bfloat16* __restrict__ Lo, int n4)
{
    int i = blockIdx.x * blockDim.x + threadIdx.x;
    if (i >= n4) return;
    float4 v = reinterpret_cast<const float4*>(X)[i];
    float vv[4] = {v.x, v.y, v.z, v.w};
    __nv_bfloat16 h[4], l[4];
    #pragma unroll
    for (int j = 0; j < 4; j++) {
        h[j] = __float2bfloat16(vv[j]);
        l[j] = __float2bfloat16(vv[j] - __bfloat162float(h[j]));
    }
    reinterpret_cast<uint2*>(Hi)[i] = *reinterpret_cast<uint2*>(h);
    reinterpret_cast<uint2*>(Lo)[i] = *reinterpret_cast<uint2*>(l);
}

// ---------------------------------------------------------------------------
// fp32 [K][N] -> transposed (bf16 hi, lo) [N][K]  (weights)
// ---------------------------------------------------------------------------
__global__ __launch_bounds__(256) void conv_split_T(
    const float* __restrict__ W, __nv_bfloat16* __restrict__ HiT,
    __nv_bfloat16* __restrict__ LoT, int K, int N)
{
    __shared__ float t[32][33];
    const int n0 = blockIdx.x * 32, k0 = blockIdx.y * 32;
    const int tx = threadIdx.x, ty = threadIdx.y;  // 32 x 8
    #pragma unroll
    for (int i = 0; i < 32; i += 8)
        t[ty + i][tx] = W[(size_t)(k0 + ty + i) * N + n0 + tx];  // t[k][n]
    __syncthreads();
    #pragma unroll
    for (int i = 0; i < 32; i += 8) {
        const float v = t[tx][ty + i];                  // (k=k0+tx, n=n0+ty+i)
        const __nv_bfloat16 h = __float2bfloat16(v);
        const __nv_bfloat16 l = __float2bfloat16(v - __bfloat162float(h));
        const size_t o = (size_t)(n0 + ty + i) * K + k0 + tx;
        HiT[o] = h;
        LoT[o] = l;
    }
}

// ---------------------------------------------------------------------------
// bf16x3-split tensor-core GEMM:  C[M,N] = A[M,K] @ Bt[N,K]^T + bias[N]
// A given as hi/lo bf16 [M][K]; B given transposed hi/lo bf16 [N][K].
// CTA tile 128x128x32, 256 thr (8 warps, 2x4), warp tile 64x32,
// mma.sync m16n8k16 bf16, 3 mmas per fragment (hh + hl + lh).
// ---------------------------------------------------------------------------
#define GBM 128
#define GBN 128
#define GBK 32
#define ASTR 40                       // padded smem row stride (bf16 elems)
#define A_CH (GBM * ASTR)             // elems per A chunk
#define B_CH (GBN * ASTR)
#define GEMM_SMEM_BYTES ((4 * A_CH + 4 * B_CH) * 2)

__device__ __forceinline__ void ldsm4(uint32_t& r0, uint32_t& r1,
                                      uint32_t& r2, uint32_t& r3, uint32_t addr) {
    asm volatile("ldmatrix.sync.aligned.m8n8.x4.shared.b16 {%0,%1,%2,%3},[%4];"
                 : "=r"(r0), "=r"(r1), "=r"(r2), "=r"(r3) : "r"(addr));
}
__device__ __forceinline__ void mma_bf16(float* d, const uint32_t* a,
                                         const uint32_t* b) {
    asm volatile(
        "mma.sync.aligned.m16n8k16.row.col.f32.bf16.bf16.f32 "
        "{%0,%1,%2,%3},{%4,%5,%6,%7},{%8,%9},{%0,%1,%2,%3};"
        : "+f"(d[0]), "+f"(d[1]), "+f"(d[2]), "+f"(d[3])
        : "r"(a[0]), "r"(a[1]), "r"(a[2]), "r"(a[3]), "r"(b[0]), "r"(b[1]));
}

__global__ __launch_bounds__(256) void gemm_bf16x3(
    const __nv_bfloat16* __restrict__ Ah, const __nv_bfloat16* __restrict__ Al,
    const __nv_bfloat16* __restrict__ Bh, const __nv_bfloat16* __restrict__ Bl,
    const float* __restrict__ bias, float* __restrict__ C,
    int M, int N, int K)
{
    extern __shared__ __nv_bfloat16 sm[];
    uint32_t sbase;
    asm("{.reg .u64 t; cvta.to.shared.u64 t, %1; cvt.u32.u64 %0, t;}"
        : "=r"(sbase) : "l"(sm));

    const int tid  = threadIdx.x;
    const int lane = tid & 31;
    const int wid  = tid >> 5;
    const int wm   = wid >> 2;        // 0..1
    const int wn   = wid & 3;         // 0..3
    const int brow = blockIdx.y;
    const int bcol = blockIdx.x;

    // gmem->smem mapping: thread covers rows (tid>>2) and +64, 8 bf16 each
    const int lr = tid >> 2;          // 0..63
    const int lc = (tid & 3) * 8;     // 0,8,16,24

    const __nv_bfloat16* Ah0 = Ah + (size_t)(brow * GBM + lr) * K + lc;
    const __nv_bfloat16* Al0 = Al + (size_t)(brow * GBM + lr) * K + lc;
    const __nv_bfloat16* Bh0 = Bh + (size_t)(bcol * GBN + lr) * K + lc;
    const __nv_bfloat16* Bl0 = Bl + (size_t)(bcol * GBN + lr) * K + lc;
    const size_t rstep = (size_t)64 * K;

    // smem chunk offsets (bf16 elems): A[buf][part], then B[buf][part]
    auto aoff = [](int buf, int part) { return (buf * 2 + part) * A_CH; };
    auto boff = [](int buf, int part) { return 4 * A_CH + (buf * 2 + part) * B_CH; };

    float acc[4][4][4] = {};

    // stage tile 0
    {
        const int so = lr * ASTR + lc;
        *reinterpret_cast<uint4*>(sm + aoff(0,0) + so) = *reinterpret_cast<const uint4*>(Ah0);
        *reinterpret_cast<uint4*>(sm + aoff(0,0) + so + 64*ASTR) = *reinterpret_cast<const uint4*>(Ah0 + rstep);
        *reinterpret_cast<uint4*>(sm + aoff(0,1) + so) = *reinterpret_cast<const uint4*>(Al0);
        *reinterpret_cast<uint4*>(sm + aoff(0,1) + so + 64*ASTR) = *reinterpret_cast<const uint4*>(Al0 + rstep);
        *reinterpret_cast<uint4*>(sm + boff(0,0) + so) = *reinterpret_cast<const uint4*>(Bh0);
        *reinterpret_cast<uint4*>(sm + boff(0,0) + so + 64*ASTR) = *reinterpret_cast<const uint4*>(Bh0 + rstep);
        *reinterpret_cast<uint4*>(sm + boff(0,1) + so) = *reinterpret_cast<const uint4*>(Bl0);
        *reinterpret_cast<uint4*>(sm + boff(0,1) + so + 64*ASTR) = *reinterpret_cast<const uint4*>(Bl0 + rstep);
    }
    __syncthreads();

    const int nK = K / GBK;
    const int mat = lane >> 3;        // ldmatrix sub-matrix index
    const int r8  = lane & 7;

    int buf = 0;
    for (int kt = 0; kt < nK; kt++) {
        uint4 pf[8];
        const bool more = (kt + 1) < nK;
        if (more) {
            const int ko = (kt + 1) * GBK;
            pf[0] = *reinterpret_cast<const uint4*>(Ah0 + ko);
            pf[1] = *reinterpret_cast<const uint4*>(Ah0 + ko + rstep);
            pf[2] = *reinterpret_cast<const uint4*>(Al0 + ko);
            pf[3] = *reinterpret_cast<const uint4*>(Al0 + ko + rstep);
            pf[4] = *reinterpret_cast<const uint4*>(Bh0 + ko);
            pf[5] = *reinterpret_cast<const uint4*>(Bh0 + ko + rstep);
            pf[6] = *reinterpret_cast<const uint4*>(Bl0 + ko);
            pf[7] = *reinterpret_cast<const uint4*>(Bl0 + ko + rstep);
        }

        #pragma unroll
        for (int ks = 0; ks < 2; ks++) {
            uint32_t ah[4][4], al[4][4], bh[4][2], bl[4][2];
            // A fragments: 4 m16 tiles
            #pragma unroll
            for (int mi = 0; mi < 4; mi++) {
                const int row = wm * 64 + mi * 16 + (mat & 1) * 8 + r8;
                const int col = ks * 16 + (mat >> 1) * 8;
                const uint32_t ah_addr = sbase + (uint32_t)(aoff(buf,0) + row * ASTR + col) * 2;
                ldsm4(ah[mi][0], ah[mi][1], ah[mi][2], ah[mi][3], ah_addr);
                ldsm4(al[mi][0], al[mi][1], al[mi][2], al[mi][3], ah_addr + A_CH * 2);
            }
            // B fragments: 2 x4 loads cover 4 n8 tiles
            #pragma unroll
            for (int nt = 0; nt < 2; nt++) {
                const int row = wn * 32 + nt * 16 + (mat >> 1) * 8 + r8;
                const int col = ks * 16 + (mat & 1) * 8;
                const uint32_t bh_addr = sbase + (uint32_t)(boff(buf,0) + row * ASTR + col) * 2;
                uint32_t r0, r1, r2, r3;
                ldsm4(r0, r1, r2, r3, bh_addr);
                bh[2*nt][0] = r0; bh[2*nt][1] = r1; bh[2*nt+1][0] = r2; bh[2*nt+1][1] = r3;
                ldsm4(r0, r1, r2, r3, bh_addr + B_CH * 2);
                bl[2*nt][0] = r0; bl[2*nt][1] = r1; bl[2*nt+1][0] = r2; bl[2*nt+1][1] = r3;
            }
            #pragma unroll
            for (int mi = 0; mi < 4; mi++)
                #pragma unroll
                for (int nj = 0; nj < 4; nj++) {
                    mma_bf16(acc[mi][nj], ah[mi], bh[nj]);
                    mma_bf16(acc[mi][nj], ah[mi], bl[nj]);
                    mma_bf16(acc[mi][nj], al[mi], bh[nj]);
                }
        }

        if (more) {
            const int nb = buf ^ 1;
            const int so = lr * ASTR + lc;
            *reinterpret_cast<uint4*>(sm + aoff(nb,0) + so)            = pf[0];
            *reinterpret_cast<uint4*>(sm + aoff(nb,0) + so + 64*ASTR)  = pf[1];
            *reinterpret_cast<uint4*>(sm + aoff(nb,1) + so)            = pf[2];
            *reinterpret_cast<uint4*>(sm + aoff(nb,1) + so + 64*ASTR)  = pf[3];
            *reinterpret_cast<uint4*>(sm + boff(nb,0) + so)            = pf[4];
            *reinterpret_cast<uint4*>(sm + boff(nb,0) + so + 64*ASTR)  = pf[5];
            *reinterpret_cast<uint4*>(sm + boff(nb,1) + so)            = pf[6];
            *reinterpret_cast<uint4*>(sm + boff(nb,1) + so + 64*ASTR)  = pf[7];
            __syncthreads();
        }
        buf ^= 1;
    }

    // epilogue: d0,d1 at (row, col..col+1); d2,d3 at (row+8, ...)
    #pragma unroll
    for (int nj = 0; nj < 4; nj++) {
        const int c = bcol * GBN + wn * 32 + nj * 8 + (lane & 3) * 2;
        const float2 bv = *reinterpret_cast<const float2*>(bias + c);
        #pragma unroll
        for (int mi = 0; mi < 4; mi++) {
            const int r0 = brow * GBM + wm * 64 + mi * 16 + (lane >> 2);
            float2 o0, o1;
            o0.x = acc[mi][nj][0] + bv.x;  o0.y = acc[mi][nj][1] + bv.y;
            o1.x = acc[mi][nj][2] + bv.x;  o1.y = acc[mi][nj][3] + bv.y;
            *reinterpret_cast<float2*>(C + (size_t)r0 * N + c)       = o0;
            *reinterpret_cast<float2*>(C + (size_t)(r0 + 8) * N + c) = o1;
        }
    }
}

// ---------------------------------------------------------------------------
// Tiled sparse-causal attention (unchanged; ~150us)
// ---------------------------------------------------------------------------
#define QS_SZ   (64 * 64)
#define KS_SZ   (64 * 256)
#define VS_STR  68
#define VS_SZ   (256 * VS_STR)
#define SS_STR  260
#define SS_SZ   (64 * SS_STR)
#define ATTN_SMEM_FLOATS (QS_SZ + KS_SZ + VS_SZ + SS_SZ + 64)
#define ATTN_SMEM_BYTES  (ATTN_SMEM_FLOATS * 4)

__global__ __launch_bounds__(256, 1) void sparse_attn_tiled(
    const float* __restrict__ qkv, float* __restrict__ out)
{
    const int bq  = blockIdx.x;
    const int h   = blockIdx.y;
    const int b   = blockIdx.z;
    const int qb  = bq >> 1;
    const int hb  = bq & 1;
    const int tid = threadIdx.x;

    const int nstr = qb * CKEEP;
    const int cnt  = nstr + 128;

    extern __shared__ float smf[];
    float* Qs   = smf;
    float* Ks   = Qs + QS_SZ;
    float* Vs   = Ks + KS_SZ;
    float* Ss   = Vs + VS_SZ;
    float* Linv = Ss + SS_SZ;

    const size_t base = (size_t)b * SEQ * (3 * EMB);
    const int q0 = qb * 128 + hb * 64;

    {
        const int r  = tid >> 2;
        const int d0 = (tid & 3) * 16;
        const float* src = qkv + base + (size_t)(q0 + r) * (3 * EMB) + h * HDIM + d0;
        #pragma unroll
        for (int i = 0; i < 4; i++) {
            float4 a = *reinterpret_cast<const float4*>(src + i * 4);
            const int d = d0 + i * 4;
            Qs[(d + 0) * 64 + r] = a.x;
            Qs[(d + 1) * 64 + r] = a.y;
            Qs[(d + 2) * 64 + r] = a.z;
            Qs[(d + 3) * 64 + r] = a.w;
        }
    }

    {
        const int j = tid;
        if (j < cnt) {
            const int key = (j < nstr)
                ? ((j >> 3) << 7) + (STRIDE_BLK - CKEEP) + (j & 7)
                : (qb << 7) + (j - nstr);
            const float* ksrc = qkv + base + (size_t)key * (3 * EMB) + EMB + h * HDIM;
            const float* vsrc = qkv + base + (size_t)key * (3 * EMB) + 2 * EMB + h * HDIM;
            #pragma unroll
            for (int i = 0; i < 16; i++) {
                float4 a = *reinterpret_cast<const float4*>(ksrc + i * 4);
                Ks[(i * 4 + 0) * 256 + j] = a.x;
                Ks[(i * 4 + 1) * 256 + j] = a.y;
                Ks[(i * 4 + 2) * 256 + j] = a.z;
                Ks[(i * 4 + 3) * 256 + j] = a.w;
                float4 v = *reinterpret_cast<const float4*>(vsrc + i * 4);
                *reinterpret_cast<float4*>(Vs + j * VS_STR + i * 4) = v;
            }
        }
    }
    __syncthreads();

    {
        const int trow = tid >> 5;
        const int tcol = tid & 31;
        float acc[8][8] = {};
        float rm[8], rn[8];
        #pragma unroll 4
        for (int k = 0; k < HDIM; k++) {
            *reinterpret_cast<float4*>(rm)     = *reinterpret_cast<const float4*>(Qs + k * 64 + trow * 8);
            *reinterpret_cast<float4*>(rm + 4) = *reinterpret_cast<const float4*>(Qs + k * 64 + trow * 8 + 4);
            *reinterpret_cast<float4*>(rn)     = *reinterpret_cast<const float4*>(Ks + k * 256 + tcol * 8);
            *reinterpret_cast<float4*>(rn + 4) = *reinterpret_cast<const float4*>(Ks + k * 256 + tcol * 8 + 4);
            #pragma unroll
            for (int i = 0; i < 8; i++)
                #pragma unroll
                for (int j = 0; j < 8; j++)
                    acc[i][j] += rm[i] * rn[j];
        }
        #pragma unroll
        for (int i = 0; i < 8; i++) {
            const int r   = trow * 8 + i;
            const int lim = nstr + hb * 64 + r;
            float* srow = Ss + r * SS_STR + tcol * 8;
            #pragma unroll
            for (int j = 0; j < 8; j++) {
                const int c = tcol * 8 + j;
                srow[j] = (c <= lim) ? acc[i][j] * 0.125f : -1e30f;
            }
        }
    }
    __syncthreads();

    {
        const int row = tid >> 2;
        const int sub = tid & 3;
        float* srow = Ss + row * SS_STR;
        float m = -1e30f;
        for (int c = sub; c < cnt; c += 4) m = fmaxf(m, srow[c]);
        m = fmaxf(m, __shfl_xor_sync(0xffffffffu, m, 1));
        m = fmaxf(m, __shfl_xor_sync(0xffffffffu, m, 2));
        float s = 0.f;
        for (int c = sub; c < cnt; c += 4) {
            const float e = __expf(srow[c] - m);
            srow[c] = e;
            s += e;
        }
        s += __shfl_xor_sync(0xffffffffu, s, 1);
        s += __shfl_xor_sync(0xffffffffu, s, 2);
        if (sub == 0) Linv[row] = 1.0f / s;
    }
    __syncthreads();

    {
        const int rg = tid >> 4;
        const int cg = tid & 15;
        float acc[4][4] = {};
        #pragma unroll 2
        for (int kk = 0; kk < cnt; kk++) {
            const float4 v = *reinterpret_cast<const float4*>(Vs + kk * VS_STR + cg * 4);
            #pragma unroll
            for (int i = 0; i < 4; i++) {
                const float p = Ss[(rg * 4 + i) * SS_STR + kk];
                acc[i][0] += p * v.x;
                acc[i][1] += p * v.y;
                acc[i][2] += p * v.z;
                acc[i][3] += p * v.w;
            }
        }
        #pragma unroll
        for (int i = 0; i < 4; i++) {
            const int r = rg * 4 + i;
            const float inv = Linv[r];
            float4 o;
            o.x = acc[i][0] * inv;
            o.y = acc[i][1] * inv;
            o.z = acc[i][2] * inv;
            o.w = acc[i][3] * inv;
            *reinterpret_cast<float4*>(
                out + (size_t)(b * SEQ + q0 + r) * EMB + h * HDIM + cg * 4) = o;
        }
    }
}

// ---------------------------------------------------------------------------
extern "C" void kernel_launch(void* const* d_in, const int* in_sizes, int n_in,
                              void* d_out, int out_size) {
    const float* hs     = (const float*)d_in[0];
    const float* W_attn = (const float*)d_in[1];
    const float* b_attn = (const float*)d_in[2];
    const float* W_proj = (const float*)d_in[3];
    const float* b_proj = (const float*)d_in[4];
    float* out = (float*)d_out;

    float *qkv, *att;
    __nv_bfloat16 *AH, *AL, *WH, *WL;
    cudaGetSymbolAddress((void**)&qkv, g_qkv);
    cudaGetSymbolAddress((void**)&att, g_att);
    cudaGetSymbolAddress((void**)&AH, g_AH);
    cudaGetSymbolAddress((void**)&AL, g_AL);
    cudaGetSymbolAddress((void**)&WH, g_WH);
    cudaGetSymbolAddress((void**)&WL, g_WL);

    static bool attr_set = false;
    if (!attr_set) {
        cudaFuncSetAttribute(sparse_attn_tiled,
                             cudaFuncAttributeMaxDynamicSharedMemorySize,
                             ATTN_SMEM_BYTES);
        cudaFuncSetAttribute(gemm_bf16x3,
                             cudaFuncAttributeMaxDynamicSharedMemorySize,
                             GEMM_SMEM_BYTES);
        attr_set = true;
    }

    const int M = BATCH * SEQ;  // 4096
    const int K = EMB;          // 1024

    // 1) convert hs -> hi/lo bf16; W_attn -> transposed hi/lo
    conv_split<<<(M * K / 4 + 255) / 256, 256>>>(hs, AH, AL, M * K / 4);
    {
        dim3 g(3 * EMB / 32, EMB / 32), t(32, 8);
        conv_split_T<<<g, t>>>(W_attn, WH, WL, K, 3 * EMB);
    }
    // 2) QKV projection (tensor cores)
    {
        dim3 grid((3 * EMB) / GBN, M / GBM);
        gemm_bf16x3<<<grid, 256, GEMM_SMEM_BYTES>>>(AH, AL, WH, WL, b_attn, qkv,
                                                    M, 3 * EMB, K);
    }
    // 3) Sparse attention
    {
        dim3 grid(32, NHEAD, BATCH);
        sparse_attn_tiled<<<grid, 256, ATTN_SMEM_BYTES>>>(qkv, att);
    }
    // 4) convert att + W_proj, then output projection
    conv_split<<<(M * K / 4 + 255) / 256, 256>>>(att, AH, AL, M * K / 4);
    {
        dim3 g(EMB / 32, EMB / 32), t(32, 8);
        conv_split_T<<<g, t>>>(W_proj, WH, WL, K, EMB);
    }
    {
        dim3 grid(EMB / GBN, M / GBM);
        gemm_bf16x3<<<grid, 256, GEMM_SMEM_BYTES>>>(AH, AL, WH, WL, b_proj, out,
                                                    M, EMB, K);
    }
}

// round 6
// speedup vs baseline: 7.1065x; 1.1827x over previous
#include <cuda_runtime.h>
#include <cuda_bf16.h>
#include <math.h>
#include <stdint.h>

// Problem constants
#define BATCH 2
#define SEQ   2048
#define EMB   1024
#define NHEAD 16
#define HDIM  64
#define STRIDE_BLK 128
#define CKEEP 8

// Scratch (device globals; no runtime allocation allowed)
__device__ float g_qkv[(size_t)BATCH * SEQ * 3 * EMB];         // [B,S,3E]
__device__ __nv_bfloat16 g_AH[(size_t)4096 * 1024];            // A hi (hs or attn-out)
__device__ __nv_bfloat16 g_AL[(size_t)4096 * 1024];            // A lo
__device__ __nv_bfloat16 g_WH[(size_t)3072 * 1024];            // W^T hi [N][K]
__device__ __nv_bfloat16 g_WL[(size_t)3072 * 1024];            // W^T lo

// ---------------------------------------------------------------------------
// helpers
// ---------------------------------------------------------------------------
__device__ __forceinline__ uint32_t bf2_pack(__nv_bfloat16 a, __nv_bfloat16 b) {
    __nv_bfloat162 v(a, b);
    return *reinterpret_cast<uint32_t*>(&v);
}
__device__ __forceinline__ void split_pair(float x, float y, uint32_t& hi, uint32_t& lo) {
    __nv_bfloat16 hx = __float2bfloat16(x), hy = __float2bfloat16(y);
    __nv_bfloat16 lx = __float2bfloat16(x - __bfloat162float(hx));
    __nv_bfloat16 ly = __float2bfloat16(y - __bfloat162float(hy));
    hi = bf2_pack(hx, hy);
    lo = bf2_pack(lx, ly);
}
__device__ __forceinline__ void ldsm4(uint32_t& r0, uint32_t& r1,
                                      uint32_t& r2, uint32_t& r3, uint32_t addr) {
    asm volatile("ldmatrix.sync.aligned.m8n8.x4.shared.b16 {%0,%1,%2,%3},[%4];"
                 : "=r"(r0), "=r"(r1), "=r"(r2), "=r"(r3) : "r"(addr));
}
__device__ __forceinline__ void mma_bf16(float* d, const uint32_t* a,
                                         const uint32_t* b) {
    asm volatile(
        "mma.sync.aligned.m16n8k16.row.col.f32.bf16.bf16.f32 "
        "{%0,%1,%2,%3},{%4,%5,%6,%7},{%8,%9},{%0,%1,%2,%3};"
        : "+f"(d[0]), "+f"(d[1]), "+f"(d[2]), "+f"(d[3])
        : "r"(a[0]), "r"(a[1]), "r"(a[2]), "r"(a[3]), "r"(b[0]), "r"(b[1]));
}
__device__ __forceinline__ uint32_t smem_u32(const void* p) {
    uint32_t a;
    asm("{.reg .u64 t; cvta.to.shared.u64 t, %1; cvt.u32.u64 %0, t;}" : "=r"(a) : "l"(p));
    return a;
}

// ---------------------------------------------------------------------------
// fp32 -> (bf16 hi, bf16 lo) split, elementwise
// ---------------------------------------------------------------------------
__global__ __launch_bounds__(256) void conv_split(
    const float* __restrict__ X, __nv_bfloat16* __restrict__ Hi,
    __nv_bfloat16* __restrict__ Lo, int n4)
{
    int i = blockIdx.x * blockDim.x + threadIdx.x;
    if (i >= n4) return;
    float4 v = reinterpret_cast<const float4*>(X)[i];
    uint32_t h0, l0, h1, l1;
    split_pair(v.x, v.y, h0, l0);
    split_pair(v.z, v.w, h1, l1);
    uint2 hh = {h0, h1}, ll = {l0, l1};
    reinterpret_cast<uint2*>(Hi)[i] = hh;
    reinterpret_cast<uint2*>(Lo)[i] = ll;
}

// ---------------------------------------------------------------------------
// fp32 [K][N] -> transposed (bf16 hi, lo) [N][K]  (weights)
// ---------------------------------------------------------------------------
__global__ __launch_bounds__(256) void conv_split_T(
    const float* __restrict__ W, __nv_bfloat16* __restrict__ HiT,
    __nv_bfloat16* __restrict__ LoT, int K, int N)
{
    __shared__ float t[32][33];
    const int n0 = blockIdx.x * 32, k0 = blockIdx.y * 32;
    const int tx = threadIdx.x, ty = threadIdx.y;  // 32 x 8
    #pragma unroll
    for (int i = 0; i < 32; i += 8)
        t[ty + i][tx] = W[(size_t)(k0 + ty + i) * N + n0 + tx];
    __syncthreads();
    #pragma unroll
    for (int i = 0; i < 32; i += 8) {
        const float v = t[tx][ty + i];
        const __nv_bfloat16 h = __float2bfloat16(v);
        const __nv_bfloat16 l = __float2bfloat16(v - __bfloat162float(h));
        const size_t o = (size_t)(n0 + ty + i) * K + k0 + tx;
        HiT[o] = h;
        LoT[o] = l;
    }
}

// ---------------------------------------------------------------------------
// bf16x3-split tensor-core GEMM:  C[M,N] = A[M,K] @ Bt[N,K]^T + bias[N]
// ---------------------------------------------------------------------------
#define GBM 128
#define GBN 128
#define GBK 32
#define ASTR 40
#define A_CH (GBM * ASTR)
#define B_CH (GBN * ASTR)
#define GEMM_SMEM_BYTES ((4 * A_CH + 4 * B_CH) * 2)

__global__ __launch_bounds__(256) void gemm_bf16x3(
    const __nv_bfloat16* __restrict__ Ah, const __nv_bfloat16* __restrict__ Al,
    const __nv_bfloat16* __restrict__ Bh, const __nv_bfloat16* __restrict__ Bl,
    const float* __restrict__ bias, float* __restrict__ C,
    int M, int N, int K)
{
    extern __shared__ __nv_bfloat16 sm[];
    uint32_t sbase = smem_u32(sm);

    const int tid  = threadIdx.x;
    const int lane = tid & 31;
    const int wid  = tid >> 5;
    const int wm   = wid >> 2;
    const int wn   = wid & 3;
    const int brow = blockIdx.y;
    const int bcol = blockIdx.x;

    const int lr = tid >> 2;
    const int lc = (tid & 3) * 8;

    const __nv_bfloat16* Ah0 = Ah + (size_t)(brow * GBM + lr) * K + lc;
    const __nv_bfloat16* Al0 = Al + (size_t)(brow * GBM + lr) * K + lc;
    const __nv_bfloat16* Bh0 = Bh + (size_t)(bcol * GBN + lr) * K + lc;
    const __nv_bfloat16* Bl0 = Bl + (size_t)(bcol * GBN + lr) * K + lc;
    const size_t rstep = (size_t)64 * K;

    auto aoff = [](int buf, int part) { return (buf * 2 + part) * A_CH; };
    auto boff = [](int buf, int part) { return 4 * A_CH + (buf * 2 + part) * B_CH; };

    float acc[4][4][4] = {};

    {
        const int so = lr * ASTR + lc;
        *reinterpret_cast<uint4*>(sm + aoff(0,0) + so) = *reinterpret_cast<const uint4*>(Ah0);
        *reinterpret_cast<uint4*>(sm + aoff(0,0) + so + 64*ASTR) = *reinterpret_cast<const uint4*>(Ah0 + rstep);
        *reinterpret_cast<uint4*>(sm + aoff(0,1) + so) = *reinterpret_cast<const uint4*>(Al0);
        *reinterpret_cast<uint4*>(sm + aoff(0,1) + so + 64*ASTR) = *reinterpret_cast<const uint4*>(Al0 + rstep);
        *reinterpret_cast<uint4*>(sm + boff(0,0) + so) = *reinterpret_cast<const uint4*>(Bh0);
        *reinterpret_cast<uint4*>(sm + boff(0,0) + so + 64*ASTR) = *reinterpret_cast<const uint4*>(Bh0 + rstep);
        *reinterpret_cast<uint4*>(sm + boff(0,1) + so) = *reinterpret_cast<const uint4*>(Bl0);
        *reinterpret_cast<uint4*>(sm + boff(0,1) + so + 64*ASTR) = *reinterpret_cast<const uint4*>(Bl0 + rstep);
    }
    __syncthreads();

    const int nK = K / GBK;
    const int mat = lane >> 3;
    const int r8  = lane & 7;

    int buf = 0;
    for (int kt = 0; kt < nK; kt++) {
        uint4 pf[8];
        const bool more = (kt + 1) < nK;
        if (more) {
            const int ko = (kt + 1) * GBK;
            pf[0] = *reinterpret_cast<const uint4*>(Ah0 + ko);
            pf[1] = *reinterpret_cast<const uint4*>(Ah0 + ko + rstep);
            pf[2] = *reinterpret_cast<const uint4*>(Al0 + ko);
            pf[3] = *reinterpret_cast<const uint4*>(Al0 + ko + rstep);
            pf[4] = *reinterpret_cast<const uint4*>(Bh0 + ko);
            pf[5] = *reinterpret_cast<const uint4*>(Bh0 + ko + rstep);
            pf[6] = *reinterpret_cast<const uint4*>(Bl0 + ko);
            pf[7] = *reinterpret_cast<const uint4*>(Bl0 + ko + rstep);
        }

        #pragma unroll
        for (int ks = 0; ks < 2; ks++) {
            uint32_t ah[4][4], al[4][4], bh[4][2], bl[4][2];
            #pragma unroll
            for (int mi = 0; mi < 4; mi++) {
                const int row = wm * 64 + mi * 16 + (mat & 1) * 8 + r8;
                const int col = ks * 16 + (mat >> 1) * 8;
                const uint32_t ah_addr = sbase + (uint32_t)(aoff(buf,0) + row * ASTR + col) * 2;
                ldsm4(ah[mi][0], ah[mi][1], ah[mi][2], ah[mi][3], ah_addr);
                ldsm4(al[mi][0], al[mi][1], al[mi][2], al[mi][3], ah_addr + A_CH * 2);
            }
            #pragma unroll
            for (int nt = 0; nt < 2; nt++) {
                const int row = wn * 32 + nt * 16 + (mat >> 1) * 8 + r8;
                const int col = ks * 16 + (mat & 1) * 8;
                const uint32_t bh_addr = sbase + (uint32_t)(boff(buf,0) + row * ASTR + col) * 2;
                uint32_t r0, r1, r2, r3;
                ldsm4(r0, r1, r2, r3, bh_addr);
                bh[2*nt][0] = r0; bh[2*nt][1] = r1; bh[2*nt+1][0] = r2; bh[2*nt+1][1] = r3;
                ldsm4(r0, r1, r2, r3, bh_addr + B_CH * 2);
                bl[2*nt][0] = r0; bl[2*nt][1] = r1; bl[2*nt+1][0] = r2; bl[2*nt+1][1] = r3;
            }
            #pragma unroll
            for (int mi = 0; mi < 4; mi++)
                #pragma unroll
                for (int nj = 0; nj < 4; nj++) {
                    mma_bf16(acc[mi][nj], ah[mi], bh[nj]);
                    mma_bf16(acc[mi][nj], ah[mi], bl[nj]);
                    mma_bf16(acc[mi][nj], al[mi], bh[nj]);
                }
        }

        if (more) {
            const int nb = buf ^ 1;
            const int so = lr * ASTR + lc;
            *reinterpret_cast<uint4*>(sm + aoff(nb,0) + so)            = pf[0];
            *reinterpret_cast<uint4*>(sm + aoff(nb,0) + so + 64*ASTR)  = pf[1];
            *reinterpret_cast<uint4*>(sm + aoff(nb,1) + so)            = pf[2];
            *reinterpret_cast<uint4*>(sm + aoff(nb,1) + so + 64*ASTR)  = pf[3];
            *reinterpret_cast<uint4*>(sm + boff(nb,0) + so)            = pf[4];
            *reinterpret_cast<uint4*>(sm + boff(nb,0) + so + 64*ASTR)  = pf[5];
            *reinterpret_cast<uint4*>(sm + boff(nb,1) + so)            = pf[6];
            *reinterpret_cast<uint4*>(sm + boff(nb,1) + so + 64*ASTR)  = pf[7];
            __syncthreads();
        }
        buf ^= 1;
    }

    #pragma unroll
    for (int nj = 0; nj < 4; nj++) {
        const int c = bcol * GBN + wn * 32 + nj * 8 + (lane & 3) * 2;
        const float2 bv = *reinterpret_cast<const float2*>(bias + c);
        #pragma unroll
        for (int mi = 0; mi < 4; mi++) {
            const int r0 = brow * GBM + wm * 64 + mi * 16 + (lane >> 2);
            float2 o0, o1;
            o0.x = acc[mi][nj][0] + bv.x;  o0.y = acc[mi][nj][1] + bv.y;
            o1.x = acc[mi][nj][2] + bv.x;  o1.y = acc[mi][nj][3] + bv.y;
            *reinterpret_cast<float2*>(C + (size_t)r0 * N + c)       = o0;
            *reinterpret_cast<float2*>(C + (size_t)(r0 + 8) * N + c) = o1;
        }
    }
}

// ---------------------------------------------------------------------------
// Tensor-core sparse-causal attention.
// One CTA per (b, h, 128-query stride block). Keys: nstr=8*qb strided + 128
// local, padded to 256. Scores via bf16x3 mma (reg accum), in-reg masked
// softmax, P@V via bf16x3 mma. Output written directly as hi/lo bf16 planes
// for the projection GEMM.
// smem (bf16 elem offsets):
//   Vt hi [64][264] @0, Vt lo @16896
//   union @33792: {Qh[128][72], Ql, Kh[256][72], Kl}  then reused as {Ph[128][264], Pl}
//   Linv (float[128]) @elem 101376
// ---------------------------------------------------------------------------
#define AT_VSTR 264
#define AT_QSTR 72
#define AT_KSTR 72
#define AT_PSTR 264
#define AT_VTH  0
#define AT_VTL  16896
#define AT_U    33792
#define AT_QH   (AT_U)
#define AT_QL   (AT_U + 9216)
#define AT_KH   (AT_U + 18432)
#define AT_KL   (AT_U + 36864)
#define AT_PH   (AT_U)
#define AT_PL   (AT_U + 33792)
#define AT_LINV 101376
#define AT_SMEM_BYTES (AT_LINV * 2 + 512)

__device__ __forceinline__ int key_map(int j, int nstr, int qb) {
    return (j < nstr) ? ((j >> 3) << 7) + (STRIDE_BLK - CKEEP) + (j & 7)
                      : (qb << 7) + (j - nstr);
}

__global__ __launch_bounds__(256, 1) void attn_tc(
    const float* __restrict__ qkv,
    __nv_bfloat16* __restrict__ OH, __nv_bfloat16* __restrict__ OL)
{
    const int qb  = blockIdx.x;   // 0..15
    const int h   = blockIdx.y;
    const int b   = blockIdx.z;
    const int tid = threadIdx.x;
    const int lane = tid & 31;
    const int wid  = tid >> 5;
    const int nstr = qb * CKEEP;
    const int cnt  = nstr + 128;
    const int q0   = qb * 128;

    extern __shared__ __nv_bfloat16 sb16[];
    float* Linv = reinterpret_cast<float*>(sb16 + AT_LINV);
    const uint32_t sbase = smem_u32(sb16);

    const size_t base = (size_t)b * SEQ * (3 * EMB);

    // --- stage Q: row=tid>>1, 32 d per thread ---
    {
        const int row = tid >> 1;
        const int d0  = (tid & 1) * 32;
        const float* src = qkv + base + (size_t)(q0 + row) * (3 * EMB) + h * HDIM + d0;
        #pragma unroll
        for (int i = 0; i < 8; i++) {
            float4 v = *reinterpret_cast<const float4*>(src + i * 4);
            uint32_t h0, l0, h1, l1;
            split_pair(v.x, v.y, h0, l0);
            split_pair(v.z, v.w, h1, l1);
            const int eo = row * AT_QSTR + d0 + i * 4;
            uint2 hh = {h0, h1}, ll = {l0, l1};
            *reinterpret_cast<uint2*>(sb16 + AT_QH + eo) = hh;
            *reinterpret_cast<uint2*>(sb16 + AT_QL + eo) = ll;
        }
    }

    // --- stage K: thread j = key slot ---
    {
        const int j = tid;
        if (j < cnt) {
            const int key = key_map(j, nstr, qb);
            const float* src = qkv + base + (size_t)key * (3 * EMB) + EMB + h * HDIM;
            #pragma unroll
            for (int i = 0; i < 16; i++) {
                float4 v = *reinterpret_cast<const float4*>(src + i * 4);
                uint32_t h0, l0, h1, l1;
                split_pair(v.x, v.y, h0, l0);
                split_pair(v.z, v.w, h1, l1);
                const int eo = j * AT_KSTR + i * 4;
                uint2 hh = {h0, h1}, ll = {l0, l1};
                *reinterpret_cast<uint2*>(sb16 + AT_KH + eo) = hh;
                *reinterpret_cast<uint2*>(sb16 + AT_KL + eo) = ll;
            }
        } else {
            const uint2 z = {0u, 0u};
            #pragma unroll
            for (int i = 0; i < 16; i++) {
                const int eo = j * AT_KSTR + i * 4;
                *reinterpret_cast<uint2*>(sb16 + AT_KH + eo) = z;
                *reinterpret_cast<uint2*>(sb16 + AT_KL + eo) = z;
            }
        }
    }

    // --- stage V transposed: threads 0..127 hi plane, 128..255 lo plane ---
    {
        const int p       = tid & 127;       // key pair index
        const bool lo_pl  = tid >= 128;
        const int vtoff   = lo_pl ? AT_VTL : AT_VTH;
        const int k0      = 2 * p;
        if (k0 < cnt) {  // cnt even
            const int keyA = key_map(k0, nstr, qb);
            const int keyB = key_map(k0 + 1, nstr, qb);
            const float* va = qkv + base + (size_t)keyA * (3 * EMB) + 2 * EMB + h * HDIM;
            const float* vb = qkv + base + (size_t)keyB * (3 * EMB) + 2 * EMB + h * HDIM;
            #pragma unroll
            for (int i = 0; i < 16; i++) {
                float4 a = *reinterpret_cast<const float4*>(va + i * 4);
                float4 c = *reinterpret_cast<const float4*>(vb + i * 4);
                float av[4] = {a.x, a.y, a.z, a.w};
                float cv[4] = {c.x, c.y, c.z, c.w};
                #pragma unroll
                for (int e = 0; e < 4; e++) {
                    uint32_t w;
                    if (!lo_pl) {
                        w = bf2_pack(__float2bfloat16(av[e]), __float2bfloat16(cv[e]));
                    } else {
                        __nv_bfloat16 ha = __float2bfloat16(av[e]);
                        __nv_bfloat16 hc = __float2bfloat16(cv[e]);
                        w = bf2_pack(__float2bfloat16(av[e] - __bfloat162float(ha)),
                                     __float2bfloat16(cv[e] - __bfloat162float(hc)));
                    }
                    *reinterpret_cast<uint32_t*>(sb16 + vtoff + (i * 4 + e) * AT_VSTR + k0) = w;
                }
            }
        } else {
            #pragma unroll
            for (int d = 0; d < 64; d++)
                *reinterpret_cast<uint32_t*>(sb16 + vtoff + d * AT_VSTR + k0) = 0u;
        }
    }
    __syncthreads();

    const int mat = lane >> 3;
    const int r8  = lane & 7;

    // --- scores: warp wid owns rows wid*16..+15, all 256 cols ---
    float sacc[32][4];
    #pragma unroll
    for (int t = 0; t < 32; t++)
        #pragma unroll
        for (int e = 0; e < 4; e++) sacc[t][e] = 0.f;

    {
        const int arow = wid * 16 + (mat & 1) * 8 + r8;
        #pragma unroll
        for (int ks = 0; ks < 4; ks++) {
            uint32_t ah[4], al[4];
            const uint32_t aaddr = sbase + (uint32_t)(AT_QH + arow * AT_QSTR + ks * 16 + (mat >> 1) * 8) * 2;
            ldsm4(ah[0], ah[1], ah[2], ah[3], aaddr);
            ldsm4(al[0], al[1], al[2], al[3], aaddr + (AT_QL - AT_QH) * 2);
            #pragma unroll
            for (int g = 0; g < 16; g++) {
                const int brow = g * 16 + (mat >> 1) * 8 + r8;
                const uint32_t baddr = sbase + (uint32_t)(AT_KH + brow * AT_KSTR + ks * 16 + (mat & 1) * 8) * 2;
                uint32_t bh[2][2], bl[2][2];
                uint32_t r0, r1, r2, r3;
                ldsm4(r0, r1, r2, r3, baddr);
                bh[0][0] = r0; bh[0][1] = r1; bh[1][0] = r2; bh[1][1] = r3;
                ldsm4(r0, r1, r2, r3, baddr + (AT_KL - AT_KH) * 2);
                bl[0][0] = r0; bl[0][1] = r1; bl[1][0] = r2; bl[1][1] = r3;
                #pragma unroll
                for (int half = 0; half < 2; half++) {
                    mma_bf16(sacc[2 * g + half], ah, bh[half]);
                    mma_bf16(sacc[2 * g + half], ah, bl[half]);
                    mma_bf16(sacc[2 * g + half], al, bh[half]);
                }
            }
        }
    }

    // --- in-register masked softmax ---
    const int r0   = lane >> 2;
    const int c0   = (lane & 3) * 2;
    const int rowA = wid * 16 + r0;
    const int rowB = rowA + 8;
    const int limA = nstr + rowA;
    const int limB = nstr + rowB;
    const float scale = 0.125f;

    float mA = -1e30f, mB = -1e30f;
    #pragma unroll
    for (int t = 0; t < 32; t++) {
        const int c = t * 8 + c0;
        sacc[t][0] = (c     <= limA) ? sacc[t][0] * scale : -1e30f;
        sacc[t][1] = (c + 1 <= limA) ? sacc[t][1] * scale : -1e30f;
        sacc[t][2] = (c     <= limB) ? sacc[t][2] * scale : -1e30f;
        sacc[t][3] = (c + 1 <= limB) ? sacc[t][3] * scale : -1e30f;
        mA = fmaxf(mA, fmaxf(sacc[t][0], sacc[t][1]));
        mB = fmaxf(mB, fmaxf(sacc[t][2], sacc[t][3]));
    }
    mA = fmaxf(mA, __shfl_xor_sync(0xffffffffu, mA, 1));
    mA = fmaxf(mA, __shfl_xor_sync(0xffffffffu, mA, 2));
    mB = fmaxf(mB, __shfl_xor_sync(0xffffffffu, mB, 1));
    mB = fmaxf(mB, __shfl_xor_sync(0xffffffffu, mB, 2));

    float sA = 0.f, sB = 0.f;
    #pragma unroll
    for (int t = 0; t < 32; t++) {
        sacc[t][0] = __expf(sacc[t][0] - mA);
        sacc[t][1] = __expf(sacc[t][1] - mA);
        sacc[t][2] = __expf(sacc[t][2] - mB);
        sacc[t][3] = __expf(sacc[t][3] - mB);
        sA += sacc[t][0] + sacc[t][1];
        sB += sacc[t][2] + sacc[t][3];
    }
    sA += __shfl_xor_sync(0xffffffffu, sA, 1);
    sA += __shfl_xor_sync(0xffffffffu, sA, 2);
    sB += __shfl_xor_sync(0xffffffffu, sB, 1);
    sB += __shfl_xor_sync(0xffffffffu, sB, 2);

    __syncthreads();   // everyone done reading Q/K before P overwrites

    // --- write P (hi/lo bf16) into union region + Linv ---
    #pragma unroll
    for (int t = 0; t < 32; t++) {
        const int c = t * 8 + c0;
        uint32_t hA, lA, hB, lB;
        split_pair(sacc[t][0], sacc[t][1], hA, lA);
        split_pair(sacc[t][2], sacc[t][3], hB, lB);
        *reinterpret_cast<uint32_t*>(sb16 + AT_PH + rowA * AT_PSTR + c) = hA;
        *reinterpret_cast<uint32_t*>(sb16 + AT_PL + rowA * AT_PSTR + c) = lA;
        *reinterpret_cast<uint32_t*>(sb16 + AT_PH + rowB * AT_PSTR + c) = hB;
        *reinterpret_cast<uint32_t*>(sb16 + AT_PL + rowB * AT_PSTR + c) = lB;
    }
    if ((lane & 3) == 0) {
        Linv[rowA] = 1.0f / sA;
        Linv[rowB] = 1.0f / sB;
    }
    __syncthreads();

    // --- O[128][64] = P @ V ---
    float pacc[8][4];
    #pragma unroll
    for (int t = 0; t < 8; t++)
        #pragma unroll
        for (int e = 0; e < 4; e++) pacc[t][e] = 0.f;

    {
        const int prow = wid * 16 + (mat & 1) * 8 + r8;
        #pragma unroll
        for (int ks = 0; ks < 16; ks++) {
            uint32_t ah[4], al[4];
            const uint32_t aaddr = sbase + (uint32_t)(AT_PH + prow * AT_PSTR + ks * 16 + (mat >> 1) * 8) * 2;
            ldsm4(ah[0], ah[1], ah[2], ah[3], aaddr);
            ldsm4(al[0], al[1], al[2], al[3], aaddr + (AT_PL - AT_PH) * 2);
            #pragma unroll
            for (int g = 0; g < 4; g++) {
                const int vrow = g * 16 + (mat >> 1) * 8 + r8;
                const uint32_t baddr = sbase + (uint32_t)(AT_VTH + vrow * AT_VSTR + ks * 16 + (mat & 1) * 8) * 2;
                uint32_t bh[2][2], bl[2][2];
                uint32_t r0_, r1_, r2_, r3_;
                ldsm4(r0_, r1_, r2_, r3_, baddr);
                bh[0][0] = r0_; bh[0][1] = r1_; bh[1][0] = r2_; bh[1][1] = r3_;
                ldsm4(r0_, r1_, r2_, r3_, baddr + (AT_VTL - AT_VTH) * 2);
                bl[0][0] = r0_; bl[0][1] = r1_; bl[1][0] = r2_; bl[1][1] = r3_;
                #pragma unroll
                for (int half = 0; half < 2; half++) {
                    mma_bf16(pacc[2 * g + half], ah, bh[half]);
                    mma_bf16(pacc[2 * g + half], ah, bl[half]);
                    mma_bf16(pacc[2 * g + half], al, bh[half]);
                }
            }
        }
    }

    // --- epilogue: normalize, split, write hi/lo planes for proj GEMM ---
    {
        const float invA = Linv[rowA];
        const float invB = Linv[rowB];
        const size_t oA = (size_t)(b * SEQ + q0 + rowA) * EMB + h * HDIM;
        const size_t oB = (size_t)(b * SEQ + q0 + rowB) * EMB + h * HDIM;
        #pragma unroll
        for (int t = 0; t < 8; t++) {
            const int d = t * 8 + c0;
            uint32_t hA, lA, hB, lB;
            split_pair(pacc[t][0] * invA, pacc[t][1] * invA, hA, lA);
            split_pair(pacc[t][2] * invB, pacc[t][3] * invB, hB, lB);
            *reinterpret_cast<uint32_t*>(OH + oA + d) = hA;
            *reinterpret_cast<uint32_t*>(OL + oA + d) = lA;
            *reinterpret_cast<uint32_t*>(OH + oB + d) = hB;
            *reinterpret_cast<uint32_t*>(OL + oB + d) = lB;
        }
    }
}

// ---------------------------------------------------------------------------
extern "C" void kernel_launch(void* const* d_in, const int* in_sizes, int n_in,
                              void* d_out, int out_size) {
    const float* hs     = (const float*)d_in[0];
    const float* W_attn = (const float*)d_in[1];
    const float* b_attn = (const float*)d_in[2];
    const float* W_proj = (const float*)d_in[3];
    const float* b_proj = (const float*)d_in[4];
    float* out = (float*)d_out;

    float *qkv;
    __nv_bfloat16 *AH, *AL, *WH, *WL;
    cudaGetSymbolAddress((void**)&qkv, g_qkv);
    cudaGetSymbolAddress((void**)&AH, g_AH);
    cudaGetSymbolAddress((void**)&AL, g_AL);
    cudaGetSymbolAddress((void**)&WH, g_WH);
    cudaGetSymbolAddress((void**)&WL, g_WL);

    static bool attr_set = false;
    if (!attr_set) {
        cudaFuncSetAttribute(gemm_bf16x3,
                             cudaFuncAttributeMaxDynamicSharedMemorySize,
                             GEMM_SMEM_BYTES);
        cudaFuncSetAttribute(attn_tc,
                             cudaFuncAttributeMaxDynamicSharedMemorySize,
                             AT_SMEM_BYTES);
        attr_set = true;
    }

    const int M = BATCH * SEQ;  // 4096
    const int K = EMB;          // 1024

    // 1) convert hs -> hi/lo bf16; W_attn -> transposed hi/lo
    conv_split<<<(M * K / 4 + 255) / 256, 256>>>(hs, AH, AL, M * K / 4);
    {
        dim3 g(3 * EMB / 32, EMB / 32), t(32, 8);
        conv_split_T<<<g, t>>>(W_attn, WH, WL, K, 3 * EMB);
    }
    // 2) QKV projection (tensor cores) -> fp32 qkv
    {
        dim3 grid((3 * EMB) / GBN, M / GBM);
        gemm_bf16x3<<<grid, 256, GEMM_SMEM_BYTES>>>(AH, AL, WH, WL, b_attn, qkv,
                                                    M, 3 * EMB, K);
    }
    // 3) Sparse attention (tensor cores) -> writes AH/AL directly
    {
        dim3 grid(16, NHEAD, BATCH);
        attn_tc<<<grid, 256, AT_SMEM_BYTES>>>(qkv, AH, AL);
    }
    // 4) W_proj conversion + output projection
    {
        dim3 g(EMB / 32, EMB / 32), t(32, 8);
        conv_split_T<<<g, t>>>(W_proj, WH, WL, K, EMB);
    }
    {
        dim3 grid(EMB / GBN, M / GBM);
        gemm_bf16x3<<<grid, 256, GEMM_SMEM_BYTES>>>(AH, AL, WH, WL, b_proj, out,
                                                    M, EMB, K);
    }
}

// round 7
// speedup vs baseline: 7.2475x; 1.0198x over previous
#include <cuda_runtime.h>
#include <cuda_bf16.h>
#include <math.h>
#include <stdint.h>

// Problem constants
#define BATCH 2
#define SEQ   2048
#define EMB   1024
#define NHEAD 16
#define HDIM  64
#define STRIDE_BLK 128
#define CKEEP 8

// Scratch (device globals; no runtime allocation allowed)
__device__ __nv_bfloat16 g_QKVH[(size_t)BATCH * SEQ * 3 * EMB];  // qkv hi plane
__device__ __nv_bfloat16 g_QKVL[(size_t)BATCH * SEQ * 3 * EMB];  // qkv lo plane
__device__ __nv_bfloat16 g_AH[(size_t)4096 * 1024];              // A hi (hs or attn-out)
__device__ __nv_bfloat16 g_AL[(size_t)4096 * 1024];              // A lo
__device__ __nv_bfloat16 g_WH[(size_t)3072 * 1024];              // W^T hi [N][K]
__device__ __nv_bfloat16 g_WL[(size_t)3072 * 1024];              // W^T lo

// ---------------------------------------------------------------------------
// helpers
// ---------------------------------------------------------------------------
__device__ __forceinline__ uint32_t bf2_pack(__nv_bfloat16 a, __nv_bfloat16 b) {
    __nv_bfloat162 v(a, b);
    return *reinterpret_cast<uint32_t*>(&v);
}
__device__ __forceinline__ void split_pair(float x, float y, uint32_t& hi, uint32_t& lo) {
    __nv_bfloat16 hx = __float2bfloat16(x), hy = __float2bfloat16(y);
    __nv_bfloat16 lx = __float2bfloat16(x - __bfloat162float(hx));
    __nv_bfloat16 ly = __float2bfloat16(y - __bfloat162float(hy));
    hi = bf2_pack(hx, hy);
    lo = bf2_pack(lx, ly);
}
__device__ __forceinline__ void ldsm4(uint32_t& r0, uint32_t& r1,
                                      uint32_t& r2, uint32_t& r3, uint32_t addr) {
    asm volatile("ldmatrix.sync.aligned.m8n8.x4.shared.b16 {%0,%1,%2,%3},[%4];"
                 : "=r"(r0), "=r"(r1), "=r"(r2), "=r"(r3) : "r"(addr));
}
__device__ __forceinline__ void mma_bf16(float* d, const uint32_t* a,
                                         const uint32_t* b) {
    asm volatile(
        "mma.sync.aligned.m16n8k16.row.col.f32.bf16.bf16.f32 "
        "{%0,%1,%2,%3},{%4,%5,%6,%7},{%8,%9},{%0,%1,%2,%3};"
        : "+f"(d[0]), "+f"(d[1]), "+f"(d[2]), "+f"(d[3])
        : "r"(a[0]), "r"(a[1]), "r"(a[2]), "r"(a[3]), "r"(b[0]), "r"(b[1]));
}
__device__ __forceinline__ uint32_t smem_u32(const void* p) {
    uint32_t a;
    asm("{.reg .u64 t; cvta.to.shared.u64 t, %1; cvt.u32.u64 %0, t;}" : "=r"(a) : "l"(p));
    return a;
}
__device__ __forceinline__ uint32_t prmt(uint32_t a, uint32_t b, uint32_t s) {
    uint32_t d;
    asm("prmt.b32 %0,%1,%2,%3;" : "=r"(d) : "r"(a), "r"(b), "r"(s));
    return d;
}

// ---------------------------------------------------------------------------
// fp32 -> (bf16 hi, bf16 lo) split, elementwise
// ---------------------------------------------------------------------------
__global__ __launch_bounds__(256) void conv_split(
    const float* __restrict__ X, __nv_bfloat16* __restrict__ Hi,
    __nv_bfloat16* __restrict__ Lo, int n4)
{
    int i = blockIdx.x * blockDim.x + threadIdx.x;
    if (i >= n4) return;
    float4 v = reinterpret_cast<const float4*>(X)[i];
    uint32_t h0, l0, h1, l1;
    split_pair(v.x, v.y, h0, l0);
    split_pair(v.z, v.w, h1, l1);
    uint2 hh = {h0, h1}, ll = {l0, l1};
    reinterpret_cast<uint2*>(Hi)[i] = hh;
    reinterpret_cast<uint2*>(Lo)[i] = ll;
}

// ---------------------------------------------------------------------------
// fp32 [K][N] -> transposed (bf16 hi, lo) [N][K]  (weights)
// ---------------------------------------------------------------------------
__global__ __launch_bounds__(256) void conv_split_T(
    const float* __restrict__ W, __nv_bfloat16* __restrict__ HiT,
    __nv_bfloat16* __restrict__ LoT, int K, int N)
{
    __shared__ float t[32][33];
    const int n0 = blockIdx.x * 32, k0 = blockIdx.y * 32;
    const int tx = threadIdx.x, ty = threadIdx.y;  // 32 x 8
    #pragma unroll
    for (int i = 0; i < 32; i += 8)
        t[ty + i][tx] = W[(size_t)(k0 + ty + i) * N + n0 + tx];
    __syncthreads();
    #pragma unroll
    for (int i = 0; i < 32; i += 8) {
        const float v = t[tx][ty + i];
        const __nv_bfloat16 h = __float2bfloat16(v);
        const __nv_bfloat16 l = __float2bfloat16(v - __bfloat162float(h));
        const size_t o = (size_t)(n0 + ty + i) * K + k0 + tx;
        HiT[o] = h;
        LoT[o] = l;
    }
}

// ---------------------------------------------------------------------------
// bf16x3-split tensor-core GEMM:  C = A @ Bt^T + bias
// If Cf32 != nullptr, writes fp32; otherwise writes bf16 hi/lo planes OH/OL.
// ---------------------------------------------------------------------------
#define GBM 128
#define GBN 128
#define GBK 32
#define ASTR 40
#define A_CH (GBM * ASTR)
#define B_CH (GBN * ASTR)
#define GEMM_SMEM_BYTES ((4 * A_CH + 4 * B_CH) * 2)

__global__ __launch_bounds__(256) void gemm_bf16x3(
    const __nv_bfloat16* __restrict__ Ah, const __nv_bfloat16* __restrict__ Al,
    const __nv_bfloat16* __restrict__ Bh, const __nv_bfloat16* __restrict__ Bl,
    const float* __restrict__ bias, float* __restrict__ Cf32,
    __nv_bfloat16* __restrict__ OH, __nv_bfloat16* __restrict__ OL,
    int M, int N, int K)
{
    extern __shared__ __nv_bfloat16 sm[];
    uint32_t sbase = smem_u32(sm);

    const int tid  = threadIdx.x;
    const int lane = tid & 31;
    const int wid  = tid >> 5;
    const int wm   = wid >> 2;
    const int wn   = wid & 3;
    const int brow = blockIdx.y;
    const int bcol = blockIdx.x;

    const int lr = tid >> 2;
    const int lc = (tid & 3) * 8;

    const __nv_bfloat16* Ah0 = Ah + (size_t)(brow * GBM + lr) * K + lc;
    const __nv_bfloat16* Al0 = Al + (size_t)(brow * GBM + lr) * K + lc;
    const __nv_bfloat16* Bh0 = Bh + (size_t)(bcol * GBN + lr) * K + lc;
    const __nv_bfloat16* Bl0 = Bl + (size_t)(bcol * GBN + lr) * K + lc;
    const size_t rstep = (size_t)64 * K;

    auto aoff = [](int buf, int part) { return (buf * 2 + part) * A_CH; };
    auto boff = [](int buf, int part) { return 4 * A_CH + (buf * 2 + part) * B_CH; };

    float acc[4][4][4] = {};

    {
        const int so = lr * ASTR + lc;
        *reinterpret_cast<uint4*>(sm + aoff(0,0) + so) = *reinterpret_cast<const uint4*>(Ah0);
        *reinterpret_cast<uint4*>(sm + aoff(0,0) + so + 64*ASTR) = *reinterpret_cast<const uint4*>(Ah0 + rstep);
        *reinterpret_cast<uint4*>(sm + aoff(0,1) + so) = *reinterpret_cast<const uint4*>(Al0);
        *reinterpret_cast<uint4*>(sm + aoff(0,1) + so + 64*ASTR) = *reinterpret_cast<const uint4*>(Al0 + rstep);
        *reinterpret_cast<uint4*>(sm + boff(0,0) + so) = *reinterpret_cast<const uint4*>(Bh0);
        *reinterpret_cast<uint4*>(sm + boff(0,0) + so + 64*ASTR) = *reinterpret_cast<const uint4*>(Bh0 + rstep);
        *reinterpret_cast<uint4*>(sm + boff(0,1) + so) = *reinterpret_cast<const uint4*>(Bl0);
        *reinterpret_cast<uint4*>(sm + boff(0,1) + so + 64*ASTR) = *reinterpret_cast<const uint4*>(Bl0 + rstep);
    }
    __syncthreads();

    const int nK = K / GBK;
    const int mat = lane >> 3;
    const int r8  = lane & 7;

    int buf = 0;
    for (int kt = 0; kt < nK; kt++) {
        uint4 pf[8];
        const bool more = (kt + 1) < nK;
        if (more) {
            const int ko = (kt + 1) * GBK;
            pf[0] = *reinterpret_cast<const uint4*>(Ah0 + ko);
            pf[1] = *reinterpret_cast<const uint4*>(Ah0 + ko + rstep);
            pf[2] = *reinterpret_cast<const uint4*>(Al0 + ko);
            pf[3] = *reinterpret_cast<const uint4*>(Al0 + ko + rstep);
            pf[4] = *reinterpret_cast<const uint4*>(Bh0 + ko);
            pf[5] = *reinterpret_cast<const uint4*>(Bh0 + ko + rstep);
            pf[6] = *reinterpret_cast<const uint4*>(Bl0 + ko);
            pf[7] = *reinterpret_cast<const uint4*>(Bl0 + ko + rstep);
        }

        #pragma unroll
        for (int ks = 0; ks < 2; ks++) {
            uint32_t ah[4][4], al[4][4], bh[4][2], bl[4][2];
            #pragma unroll
            for (int mi = 0; mi < 4; mi++) {
                const int row = wm * 64 + mi * 16 + (mat & 1) * 8 + r8;
                const int col = ks * 16 + (mat >> 1) * 8;
                const uint32_t ah_addr = sbase + (uint32_t)(aoff(buf,0) + row * ASTR + col) * 2;
                ldsm4(ah[mi][0], ah[mi][1], ah[mi][2], ah[mi][3], ah_addr);
                ldsm4(al[mi][0], al[mi][1], al[mi][2], al[mi][3], ah_addr + A_CH * 2);
            }
            #pragma unroll
            for (int nt = 0; nt < 2; nt++) {
                const int row = wn * 32 + nt * 16 + (mat >> 1) * 8 + r8;
                const int col = ks * 16 + (mat & 1) * 8;
                const uint32_t bh_addr = sbase + (uint32_t)(boff(buf,0) + row * ASTR + col) * 2;
                uint32_t r0, r1, r2, r3;
                ldsm4(r0, r1, r2, r3, bh_addr);
                bh[2*nt][0] = r0; bh[2*nt][1] = r1; bh[2*nt+1][0] = r2; bh[2*nt+1][1] = r3;
                ldsm4(r0, r1, r2, r3, bh_addr + B_CH * 2);
                bl[2*nt][0] = r0; bl[2*nt][1] = r1; bl[2*nt+1][0] = r2; bl[2*nt+1][1] = r3;
            }
            #pragma unroll
            for (int mi = 0; mi < 4; mi++)
                #pragma unroll
                for (int nj = 0; nj < 4; nj++) {
                    mma_bf16(acc[mi][nj], ah[mi], bh[nj]);
                    mma_bf16(acc[mi][nj], ah[mi], bl[nj]);
                    mma_bf16(acc[mi][nj], al[mi], bh[nj]);
                }
        }

        if (more) {
            const int nb = buf ^ 1;
            const int so = lr * ASTR + lc;
            *reinterpret_cast<uint4*>(sm + aoff(nb,0) + so)            = pf[0];
            *reinterpret_cast<uint4*>(sm + aoff(nb,0) + so + 64*ASTR)  = pf[1];
            *reinterpret_cast<uint4*>(sm + aoff(nb,1) + so)            = pf[2];
            *reinterpret_cast<uint4*>(sm + aoff(nb,1) + so + 64*ASTR)  = pf[3];
            *reinterpret_cast<uint4*>(sm + boff(nb,0) + so)            = pf[4];
            *reinterpret_cast<uint4*>(sm + boff(nb,0) + so + 64*ASTR)  = pf[5];
            *reinterpret_cast<uint4*>(sm + boff(nb,1) + so)            = pf[6];
            *reinterpret_cast<uint4*>(sm + boff(nb,1) + so + 64*ASTR)  = pf[7];
            __syncthreads();
        }
        buf ^= 1;
    }

    #pragma unroll
    for (int nj = 0; nj < 4; nj++) {
        const int c = bcol * GBN + wn * 32 + nj * 8 + (lane & 3) * 2;
        const float2 bv = *reinterpret_cast<const float2*>(bias + c);
        #pragma unroll
        for (int mi = 0; mi < 4; mi++) {
            const int r0 = brow * GBM + wm * 64 + mi * 16 + (lane >> 2);
            float2 o0, o1;
            o0.x = acc[mi][nj][0] + bv.x;  o0.y = acc[mi][nj][1] + bv.y;
            o1.x = acc[mi][nj][2] + bv.x;  o1.y = acc[mi][nj][3] + bv.y;
            if (Cf32) {
                *reinterpret_cast<float2*>(Cf32 + (size_t)r0 * N + c)       = o0;
                *reinterpret_cast<float2*>(Cf32 + (size_t)(r0 + 8) * N + c) = o1;
            } else {
                uint32_t h0, l0, h1, l1;
                split_pair(o0.x, o0.y, h0, l0);
                split_pair(o1.x, o1.y, h1, l1);
                const size_t e0 = (size_t)r0 * N + c;
                const size_t e1 = (size_t)(r0 + 8) * N + c;
                *reinterpret_cast<uint32_t*>(OH + e0) = h0;
                *reinterpret_cast<uint32_t*>(OL + e0) = l0;
                *reinterpret_cast<uint32_t*>(OH + e1) = h1;
                *reinterpret_cast<uint32_t*>(OL + e1) = l1;
            }
        }
    }
}

// ---------------------------------------------------------------------------
// Tensor-core sparse-causal attention, reading prebuilt bf16 hi/lo qkv planes.
// One CTA per (b, h, 128-query stride block); work bounded by gmax=ceil(cnt/16).
// ---------------------------------------------------------------------------
#define AT_VSTR 264
#define AT_QSTR 72
#define AT_KSTR 72
#define AT_PSTR 264
#define AT_VTH  0
#define AT_VTL  16896
#define AT_U    33792
#define AT_QH   (AT_U)
#define AT_QL   (AT_U + 9216)
#define AT_KH   (AT_U + 18432)
#define AT_KL   (AT_U + 36864)
#define AT_PH   (AT_U)
#define AT_PL   (AT_U + 33792)
#define AT_LINV 101376
#define AT_SMEM_BYTES (AT_LINV * 2 + 512)

__device__ __forceinline__ int key_map(int j, int nstr, int qb) {
    return (j < nstr) ? ((j >> 3) << 7) + (STRIDE_BLK - CKEEP) + (j & 7)
                      : (qb << 7) + (j - nstr);
}

__global__ __launch_bounds__(256, 1) void attn_tc(
    const __nv_bfloat16* __restrict__ QKVH, const __nv_bfloat16* __restrict__ QKVL,
    __nv_bfloat16* __restrict__ OH, __nv_bfloat16* __restrict__ OL)
{
    const int qb  = 15 - blockIdx.x;   // heavy blocks first
    const int h   = blockIdx.y;
    const int b   = blockIdx.z;
    const int tid = threadIdx.x;
    const int lane = tid & 31;
    const int wid  = tid >> 5;
    const int nstr = qb * CKEEP;
    const int cnt  = nstr + 128;
    const int gmax = (cnt + 15) >> 4;  // 8..16
    const int q0   = qb * 128;

    extern __shared__ __nv_bfloat16 sb16[];
    float* Linv = reinterpret_cast<float*>(sb16 + AT_LINV);
    const uint32_t sbase = smem_u32(sb16);

    const size_t base = (size_t)b * SEQ * (3 * EMB);

    // --- stage Q (hi/lo): row = tid>>1, 32 elems per thread ---
    {
        const int row = tid >> 1;
        const int d0  = (tid & 1) * 32;
        const size_t g = base + (size_t)(q0 + row) * (3 * EMB) + h * HDIM + d0;
        const int eo = row * AT_QSTR + d0;
        #pragma unroll
        for (int i = 0; i < 4; i++) {
            *reinterpret_cast<uint4*>(sb16 + AT_QH + eo + i * 8) =
                *reinterpret_cast<const uint4*>(QKVH + g + i * 8);
            *reinterpret_cast<uint4*>(sb16 + AT_QL + eo + i * 8) =
                *reinterpret_cast<const uint4*>(QKVL + g + i * 8);
        }
    }

    // --- stage K (hi/lo): thread j = key slot ---
    {
        const int j = tid;
        if (j < cnt) {
            const int key = key_map(j, nstr, qb);
            const size_t g = base + (size_t)key * (3 * EMB) + EMB + h * HDIM;
            const int eo = j * AT_KSTR;
            #pragma unroll
            for (int i = 0; i < 8; i++) {
                *reinterpret_cast<uint4*>(sb16 + AT_KH + eo + i * 8) =
                    *reinterpret_cast<const uint4*>(QKVH + g + i * 8);
                *reinterpret_cast<uint4*>(sb16 + AT_KL + eo + i * 8) =
                    *reinterpret_cast<const uint4*>(QKVL + g + i * 8);
            }
        } else if (j < 16 * gmax) {
            const uint4 z = {0u, 0u, 0u, 0u};
            const int eo = j * AT_KSTR;
            #pragma unroll
            for (int i = 0; i < 8; i++) {
                *reinterpret_cast<uint4*>(sb16 + AT_KH + eo + i * 8) = z;
                *reinterpret_cast<uint4*>(sb16 + AT_KL + eo + i * 8) = z;
            }
        }
    }

    // --- stage V transposed via PRMT: threads 0..127 hi plane, 128..255 lo ---
    {
        const int p      = tid & 127;
        const bool lo_pl = tid >= 128;
        const int vtoff  = lo_pl ? AT_VTL : AT_VTH;
        const int k0     = 2 * p;
        if (k0 < cnt) {
            const __nv_bfloat16* plane = lo_pl ? QKVL : QKVH;
            const int keyA = key_map(k0, nstr, qb);
            const int keyB = key_map(k0 + 1, nstr, qb);
            const __nv_bfloat16* ra = plane + base + (size_t)keyA * (3 * EMB) + 2 * EMB + h * HDIM;
            const __nv_bfloat16* rb = plane + base + (size_t)keyB * (3 * EMB) + 2 * EMB + h * HDIM;
            #pragma unroll
            for (int i = 0; i < 8; i++) {
                uint4 a = *reinterpret_cast<const uint4*>(ra + i * 8);
                uint4 c = *reinterpret_cast<const uint4*>(rb + i * 8);
                const uint32_t aw[4] = {a.x, a.y, a.z, a.w};
                const uint32_t cw[4] = {c.x, c.y, c.z, c.w};
                #pragma unroll
                for (int e = 0; e < 4; e++) {
                    const int d = i * 8 + e * 2;
                    *reinterpret_cast<uint32_t*>(sb16 + vtoff + d * AT_VSTR + k0) =
                        prmt(aw[e], cw[e], 0x5410u);
                    *reinterpret_cast<uint32_t*>(sb16 + vtoff + (d + 1) * AT_VSTR + k0) =
                        prmt(aw[e], cw[e], 0x7632u);
                }
            }
        } else if (k0 < 16 * gmax) {
            #pragma unroll
            for (int d = 0; d < 64; d++)
                *reinterpret_cast<uint32_t*>(sb16 + vtoff + d * AT_VSTR + k0) = 0u;
        }
    }
    __syncthreads();

    const int mat = lane >> 3;
    const int r8  = lane & 7;

    // --- scores: warp wid owns rows wid*16..+15 ---
    float sacc[32][4];
    #pragma unroll
    for (int t = 0; t < 32; t++)
        #pragma unroll
        for (int e = 0; e < 4; e++) sacc[t][e] = 0.f;

    {
        const int arow = wid * 16 + (mat & 1) * 8 + r8;
        #pragma unroll
        for (int ks = 0; ks < 4; ks++) {
            uint32_t ah[4], al[4];
            const uint32_t aaddr = sbase + (uint32_t)(AT_QH + arow * AT_QSTR + ks * 16 + (mat >> 1) * 8) * 2;
            ldsm4(ah[0], ah[1], ah[2], ah[3], aaddr);
            ldsm4(al[0], al[1], al[2], al[3], aaddr + (AT_QL - AT_QH) * 2);
            #pragma unroll
            for (int g = 0; g < 16; g++) {
                if (g < gmax) {
                    const int brow = g * 16 + (mat >> 1) * 8 + r8;
                    const uint32_t baddr = sbase + (uint32_t)(AT_KH + brow * AT_KSTR + ks * 16 + (mat & 1) * 8) * 2;
                    uint32_t bh[2][2], bl[2][2];
                    uint32_t r0, r1, r2, r3;
                    ldsm4(r0, r1, r2, r3, baddr);
                    bh[0][0] = r0; bh[0][1] = r1; bh[1][0] = r2; bh[1][1] = r3;
                    ldsm4(r0, r1, r2, r3, baddr + (AT_KL - AT_KH) * 2);
                    bl[0][0] = r0; bl[0][1] = r1; bl[1][0] = r2; bl[1][1] = r3;
                    #pragma unroll
                    for (int half = 0; half < 2; half++) {
                        mma_bf16(sacc[2 * g + half], ah, bh[half]);
                        mma_bf16(sacc[2 * g + half], ah, bl[half]);
                        mma_bf16(sacc[2 * g + half], al, bh[half]);
                    }
                }
            }
        }
    }

    // --- in-register masked softmax (only t < 2*gmax computed) ---
    const int r0   = lane >> 2;
    const int c0   = (lane & 3) * 2;
    const int rowA = wid * 16 + r0;
    const int rowB = rowA + 8;
    const int limA = nstr + rowA;
    const int limB = nstr + rowB;
    const float scale = 0.125f;

    float mA = -1e30f, mB = -1e30f;
    #pragma unroll
    for (int t = 0; t < 32; t++) {
        if (t < 2 * gmax) {
            const int c = t * 8 + c0;
            sacc[t][0] = (c     <= limA) ? sacc[t][0] * scale : -1e30f;
            sacc[t][1] = (c + 1 <= limA) ? sacc[t][1] * scale : -1e30f;
            sacc[t][2] = (c     <= limB) ? sacc[t][2] * scale : -1e30f;
            sacc[t][3] = (c + 1 <= limB) ? sacc[t][3] * scale : -1e30f;
            mA = fmaxf(mA, fmaxf(sacc[t][0], sacc[t][1]));
            mB = fmaxf(mB, fmaxf(sacc[t][2], sacc[t][3]));
        }
    }
    mA = fmaxf(mA, __shfl_xor_sync(0xffffffffu, mA, 1));
    mA = fmaxf(mA, __shfl_xor_sync(0xffffffffu, mA, 2));
    mB = fmaxf(mB, __shfl_xor_sync(0xffffffffu, mB, 1));
    mB = fmaxf(mB, __shfl_xor_sync(0xffffffffu, mB, 2));

    float sA = 0.f, sB = 0.f;
    #pragma unroll
    for (int t = 0; t < 32; t++) {
        if (t < 2 * gmax) {
            sacc[t][0] = __expf(sacc[t][0] - mA);
            sacc[t][1] = __expf(sacc[t][1] - mA);
            sacc[t][2] = __expf(sacc[t][2] - mB);
            sacc[t][3] = __expf(sacc[t][3] - mB);
            sA += sacc[t][0] + sacc[t][1];
            sB += sacc[t][2] + sacc[t][3];
        }
    }
    sA += __shfl_xor_sync(0xffffffffu, sA, 1);
    sA += __shfl_xor_sync(0xffffffffu, sA, 2);
    sB += __shfl_xor_sync(0xffffffffu, sB, 1);
    sB += __shfl_xor_sync(0xffffffffu, sB, 2);

    __syncthreads();   // Q/K reads done before P overwrites

    // --- write P (hi/lo) + Linv ---
    #pragma unroll
    for (int t = 0; t < 32; t++) {
        if (t < 2 * gmax) {
            const int c = t * 8 + c0;
            uint32_t hA, lA, hB, lB;
            split_pair(sacc[t][0], sacc[t][1], hA, lA);
            split_pair(sacc[t][2], sacc[t][3], hB, lB);
            *reinterpret_cast<uint32_t*>(sb16 + AT_PH + rowA * AT_PSTR + c) = hA;
            *reinterpret_cast<uint32_t*>(sb16 + AT_PL + rowA * AT_PSTR + c) = lA;
            *reinterpret_cast<uint32_t*>(sb16 + AT_PH + rowB * AT_PSTR + c) = hB;
            *reinterpret_cast<uint32_t*>(sb16 + AT_PL + rowB * AT_PSTR + c) = lB;
        }
    }
    if ((lane & 3) == 0) {
        Linv[rowA] = 1.0f / sA;
        Linv[rowB] = 1.0f / sB;
    }
    __syncthreads();

    // --- O[128][64] = P @ V ---
    float pacc[8][4];
    #pragma unroll
    for (int t = 0; t < 8; t++)
        #pragma unroll
        for (int e = 0; e < 4; e++) pacc[t][e] = 0.f;

    {
        const int prow = wid * 16 + (mat & 1) * 8 + r8;
        #pragma unroll
        for (int ks = 0; ks < 16; ks++) {
            if (ks < gmax) {
                uint32_t ah[4], al[4];
                const uint32_t aaddr = sbase + (uint32_t)(AT_PH + prow * AT_PSTR + ks * 16 + (mat >> 1) * 8) * 2;
                ldsm4(ah[0], ah[1], ah[2], ah[3], aaddr);
                ldsm4(al[0], al[1], al[2], al[3], aaddr + (AT_PL - AT_PH) * 2);
                #pragma unroll
                for (int g = 0; g < 4; g++) {
                    const int vrow = g * 16 + (mat >> 1) * 8 + r8;
                    const uint32_t baddr = sbase + (uint32_t)(AT_VTH + vrow * AT_VSTR + ks * 16 + (mat & 1) * 8) * 2;
                    uint32_t bh[2][2], bl[2][2];
                    uint32_t r0_, r1_, r2_, r3_;
                    ldsm4(r0_, r1_, r2_, r3_, baddr);
                    bh[0][0] = r0_; bh[0][1] = r1_; bh[1][0] = r2_; bh[1][1] = r3_;
                    ldsm4(r0_, r1_, r2_, r3_, baddr + (AT_VTL - AT_VTH) * 2);
                    bl[0][0] = r0_; bl[0][1] = r1_; bl[1][0] = r2_; bl[1][1] = r3_;
                    #pragma unroll
                    for (int half = 0; half < 2; half++) {
                        mma_bf16(pacc[2 * g + half], ah, bh[half]);
                        mma_bf16(pacc[2 * g + half], ah, bl[half]);
                        mma_bf16(pacc[2 * g + half], al, bh[half]);
                    }
                }
            }
        }
    }

    // --- epilogue: normalize, split, write hi/lo planes for proj GEMM ---
    {
        const float invA = Linv[rowA];
        const float invB = Linv[rowB];
        const size_t oA = (size_t)(b * SEQ + q0 + rowA) * EMB + h * HDIM;
        const size_t oB = (size_t)(b * SEQ + q0 + rowB) * EMB + h * HDIM;
        #pragma unroll
        for (int t = 0; t < 8; t++) {
            const int d = t * 8 + c0;
            uint32_t hA, lA, hB, lB;
            split_pair(pacc[t][0] * invA, pacc[t][1] * invA, hA, lA);
            split_pair(pacc[t][2] * invB, pacc[t][3] * invB, hB, lB);
            *reinterpret_cast<uint32_t*>(OH + oA + d) = hA;
            *reinterpret_cast<uint32_t*>(OL + oA + d) = lA;
            *reinterpret_cast<uint32_t*>(OH + oB + d) = hB;
            *reinterpret_cast<uint32_t*>(OL + oB + d) = lB;
        }
    }
}

// ---------------------------------------------------------------------------
extern "C" void kernel_launch(void* const* d_in, const int* in_sizes, int n_in,
                              void* d_out, int out_size) {
    const float* hs     = (const float*)d_in[0];
    const float* W_attn = (const float*)d_in[1];
    const float* b_attn = (const float*)d_in[2];
    const float* W_proj = (const float*)d_in[3];
    const float* b_proj = (const float*)d_in[4];
    float* out = (float*)d_out;

    __nv_bfloat16 *QKVH, *QKVL, *AH, *AL, *WH, *WL;
    cudaGetSymbolAddress((void**)&QKVH, g_QKVH);
    cudaGetSymbolAddress((void**)&QKVL, g_QKVL);
    cudaGetSymbolAddress((void**)&AH, g_AH);
    cudaGetSymbolAddress((void**)&AL, g_AL);
    cudaGetSymbolAddress((void**)&WH, g_WH);
    cudaGetSymbolAddress((void**)&WL, g_WL);

    static bool attr_set = false;
    if (!attr_set) {
        cudaFuncSetAttribute(gemm_bf16x3,
                             cudaFuncAttributeMaxDynamicSharedMemorySize,
                             GEMM_SMEM_BYTES);
        cudaFuncSetAttribute(attn_tc,
                             cudaFuncAttributeMaxDynamicSharedMemorySize,
                             AT_SMEM_BYTES);
        attr_set = true;
    }

    const int M = BATCH * SEQ;  // 4096
    const int K = EMB;          // 1024

    // 1) convert hs -> hi/lo bf16; W_attn -> transposed hi/lo
    conv_split<<<(M * K / 4 + 255) / 256, 256>>>(hs, AH, AL, M * K / 4);
    {
        dim3 g(3 * EMB / 32, EMB / 32), t(32, 8);
        conv_split_T<<<g, t>>>(W_attn, WH, WL, K, 3 * EMB);
    }
    // 2) QKV projection -> bf16 hi/lo planes (split fused into epilogue)
    {
        dim3 grid((3 * EMB) / GBN, M / GBM);
        gemm_bf16x3<<<grid, 256, GEMM_SMEM_BYTES>>>(AH, AL, WH, WL, b_attn,
                                                    nullptr, QKVH, QKVL,
                                                    M, 3 * EMB, K);
    }
    // 3) Sparse attention (tensor cores) -> writes AH/AL directly
    {
        dim3 grid(16, NHEAD, BATCH);
        attn_tc<<<grid, 256, AT_SMEM_BYTES>>>(QKVH, QKVL, AH, AL);
    }
    // 4) W_proj conversion + output projection (fp32 out)
    {
        dim3 g(EMB / 32, EMB / 32), t(32, 8);
        conv_split_T<<<g, t>>>(W_proj, WH, WL, K, EMB);
    }
    {
        dim3 grid(EMB / GBN, M / GBM);
        gemm_bf16x3<<<grid, 256, GEMM_SMEM_BYTES>>>(AH, AL, WH, WL, b_proj,
                                                    out, nullptr, nullptr,
                                                    M, EMB, K);
    }
}